// round 4
// baseline (speedup 1.0000x reference)
#include <cuda_runtime.h>
#include <cuda_bf16.h>
#include <math.h>
#include <stdint.h>

#define DEV_INLINE __device__ __forceinline__

namespace cfg {
constexpr int N = 20000;
constexpr int E = 600000;
constexpr int D = 512;
constexpr int H = 8;
constexpr int HID = 1024;

// ---- fp32 scratch offsets ----
constexpr long OFF_QK   = 0;                          // N*1024 (q | k)
constexpr long OFF_LOG  = OFF_QK  + (long)N * 1024;   // E*8
constexpr long OFF_MXU  = OFF_LOG + (long)E * 8;      // N*8
constexpr long OFF_MX   = OFF_MXU + (long)N * 8;      // N*8
constexpr long OFF_DEN  = OFF_MX  + (long)N * 8;      // N*8
constexpr long OFF_ATT  = OFF_DEN + (long)N * 8;      // N*24 (unnormalized sums)
constexpr long OFF_RAWF = OFF_ATT + (long)N * 24;     // N*1024 (pre-gelu forces h1, partial)
constexpr long OFF_H2E  = OFF_RAWF+ (long)N * 1024;   // N*1024
constexpr long OFF_H2F  = OFF_H2E + (long)N * 1024;   // N*1024
constexpr long OFF_BQK  = OFF_H2F + (long)N * 1024;   // 1024
constexpr long OFF_BIN  = OFF_BQK + 1024;             // 2048
constexpr long OFF_BEH  = OFF_BIN + 2048;             // 1024
constexpr long OFF_BFH  = OFF_BEH + 1024;             // 1024
constexpr long FTOTAL   = OFF_BFH + 1024;

// ---- bf16 scratch offsets ----
constexpr long B_ZATT_HI = 0;
constexpr long B_ZATT_LO = B_ZATT_HI + (long)N * D;
constexpr long B_ZMLP_HI = B_ZATT_LO + (long)N * D;
constexpr long B_ZMLP_LO = B_ZMLP_HI + (long)N * D;
constexpr long B_H1E_HI  = B_ZMLP_LO + (long)N * D;
constexpr long B_H1E_LO  = B_H1E_HI  + (long)N * HID;
constexpr long B_H1F_HI  = B_H1E_LO  + (long)N * HID;
constexpr long B_H1F_LO  = B_H1F_HI  + (long)N * HID;
constexpr long B_WQK_HI  = B_H1F_LO  + (long)N * HID;   // [1024, 512]
constexpr long B_WQK_LO  = B_WQK_HI  + 1024L * 512;
constexpr long B_WIN_HI  = B_WQK_LO  + 1024L * 512;     // [2048, 512]
constexpr long B_WIN_LO  = B_WIN_HI  + 2048L * 512;
constexpr long B_WEH_HI  = B_WIN_LO  + 2048L * 512;     // [1024, 1024]
constexpr long B_WEH_LO  = B_WEH_HI  + 1024L * 1024;
constexpr long B_WFH_HI  = B_WEH_LO  + 1024L * 1024;
constexpr long B_WFH_LO  = B_WFH_HI  + 1024L * 1024;
constexpr long BTOTAL    = B_WFH_LO  + 1024L * 1024;
}

__device__ float g_f[cfg::FTOTAL];
__device__ __nv_bfloat16 g_bf[cfg::BTOTAL];

// ===========================================================================
// helpers
// ===========================================================================
DEV_INLINE float gelu_tanh(float x) {
    float x3 = x * x * x;
    float t = tanhf(0.7978845608028654f * (x + 0.044715f * x3));
    return 0.5f * x * (1.0f + t);
}
DEV_INLINE void split_bf16(float v, __nv_bfloat16& h, __nv_bfloat16& l) {
    h = __float2bfloat16(v);
    l = __float2bfloat16(v - __bfloat162float(h));
}
DEV_INLINE unsigned f2u(float f) {
    unsigned u = __float_as_uint(f);
    return (u & 0x80000000u) ? ~u : (u | 0x80000000u);
}
DEV_INLINE float u2f(unsigned u) {
    return __uint_as_float((u & 0x80000000u) ? (u ^ 0x80000000u) : ~u);
}
DEV_INLINE uint32_t smem_u32(const void* p) {
    uint32_t a;
    asm("{ .reg .u64 t; cvta.to.shared.u64 t, %1; cvt.u32.u64 %0, t; }" : "=r"(a) : "l"(p));
    return a;
}
DEV_INLINE void cp16(uint32_t dst, const void* src, int szbytes) {
    asm volatile("cp.async.cg.shared.global [%0], [%1], 16, %2;\n" :: "r"(dst), "l"(src), "r"(szbytes));
}
DEV_INLINE void cp_commit() { asm volatile("cp.async.commit_group;\n"); }
template <int NN>
DEV_INLINE void cp_wait() { asm volatile("cp.async.wait_group %0;\n" :: "n"(NN) : "memory"); }

DEV_INLINE void ldsm_x4(uint32_t& r0, uint32_t& r1, uint32_t& r2, uint32_t& r3, uint32_t addr) {
    asm volatile("ldmatrix.sync.aligned.m8n8.x4.shared.b16 {%0,%1,%2,%3}, [%4];"
                 : "=r"(r0), "=r"(r1), "=r"(r2), "=r"(r3) : "r"(addr));
}
DEV_INLINE void mma16816(float* c, const uint32_t* a, const uint32_t* b) {
    asm volatile("mma.sync.aligned.m16n8k16.row.col.f32.bf16.bf16.f32 "
                 "{%0,%1,%2,%3}, {%4,%5,%6,%7}, {%8,%9}, {%0,%1,%2,%3};"
                 : "+f"(c[0]), "+f"(c[1]), "+f"(c[2]), "+f"(c[3])
                 : "r"(a[0]), "r"(a[1]), "r"(a[2]), "r"(a[3]), "r"(b[0]), "r"(b[1]));
}

// ===========================================================================
// split-bf16 HMMA GEMM: acc = A@B^T (3-term compensation)
// MODE 0: C fp32 = acc + bias                       (QK projection)
// MODE 2: C fp32 = (resHi+resLo) + gelu(acc+bias)   (hidden residual blocks)
// MODE 3: col<1024: gelu+split-bf16 -> oHi/oLo ; col>=1024: raw fp32 -> cOff
// CTA tile 128x128, BK=32, 8 warps (4m x 2n), 2-stage cp.async
// ===========================================================================
constexpr int PADK = 40;                      // 32 elems + 8 pad (80B row stride)
constexpr int MAT_BYTES = 128 * PADK * 2;     // 10240 per matrix
constexpr int STG_BYTES = 4 * MAT_BYTES;      // 40960 per stage
constexpr int GEMM_SMEM = 2 * STG_BYTES;      // 81920

template <int MODE>
__global__ __launch_bounds__(256) void tc_gemm(
    long aHi, long aLo, long bHi, long bLo, long biasOff,
    long resHi, long resLo, long cOff, long oHi, long oLo,
    int M, int Nc, int K)
{
    extern __shared__ char smem[];
    const uint32_t sb = smem_u32(smem);
    const int tid = threadIdx.x;
    const int wid = tid >> 5;
    const int lane = tid & 31;
    const int row0 = blockIdx.y * 128;
    const int col0 = blockIdx.x * 128;
    const int wm = wid & 3;
    const int wn = wid >> 2;

    const __nv_bfloat16* Ah = g_bf + aHi;
    const __nv_bfloat16* Al = g_bf + aLo;
    const __nv_bfloat16* Bh = g_bf + bHi;
    const __nv_bfloat16* Bl = g_bf + bLo;

    const int nChunks = K >> 5;

    auto load_stage = [&](int stage, int chunk) {
        const long k0 = (long)chunk << 5;
        const uint32_t base = sb + stage * STG_BYTES;
#pragma unroll
        for (int j = 0; j < 2; j++) {
            int i = tid + j * 256;
            int r = i >> 2;
            int seg = i & 3;
            uint32_t so = r * 80 + seg * 16;
            bool va = (row0 + r) < M;
            long ar = va ? (long)(row0 + r) : 0;
            cp16(base + so,                 Ah + ar * K + k0 + seg * 8, va ? 16 : 0);
            cp16(base + MAT_BYTES + so,     Al + ar * K + k0 + seg * 8, va ? 16 : 0);
            long br = (long)(col0 + r);
            cp16(base + 2 * MAT_BYTES + so, Bh + br * K + k0 + seg * 8, 16);
            cp16(base + 3 * MAT_BYTES + so, Bl + br * K + k0 + seg * 8, 16);
        }
    };

    float acc[2][8][4];
#pragma unroll
    for (int mt = 0; mt < 2; mt++)
#pragma unroll
        for (int nt = 0; nt < 8; nt++)
#pragma unroll
            for (int q = 0; q < 4; q++) acc[mt][nt][q] = 0.f;

    const int aRowOff = (lane & 7) + 8 * ((lane >> 3) & 1);
    const int aKbyte  = 16 * (lane >> 4);
    const int bRowOff = (lane & 7) + 8 * (lane >> 4);
    const int bKbyte  = 16 * ((lane >> 3) & 1);

    load_stage(0, 0);
    cp_commit();

    for (int c = 0; c < nChunks; c++) {
        if (c + 1 < nChunks) {
            load_stage((c + 1) & 1, c + 1);
            cp_commit();
            cp_wait<1>();
        } else {
            cp_wait<0>();
        }
        __syncthreads();

        const uint32_t st = sb + (c & 1) * STG_BYTES;
        const uint32_t baseAh = st;
        const uint32_t baseAl = st + MAT_BYTES;
        const uint32_t baseBh = st + 2 * MAT_BYTES;
        const uint32_t baseBl = st + 3 * MAT_BYTES;

#pragma unroll
        for (int kt = 0; kt < 2; kt++) {
            const int kb = kt * 32;
            uint32_t ah[2][4], al[2][4];
#pragma unroll
            for (int mt = 0; mt < 2; mt++) {
                uint32_t ro = (wm * 32 + mt * 16 + aRowOff) * 80 + kb + aKbyte;
                ldsm_x4(ah[mt][0], ah[mt][1], ah[mt][2], ah[mt][3], baseAh + ro);
                ldsm_x4(al[mt][0], al[mt][1], al[mt][2], al[mt][3], baseAl + ro);
            }
            uint32_t bh[8][2], bl[8][2];
#pragma unroll
            for (int nt2 = 0; nt2 < 4; nt2++) {
                uint32_t ro = (wn * 64 + nt2 * 16 + bRowOff) * 80 + kb + bKbyte;
                ldsm_x4(bh[2 * nt2][0], bh[2 * nt2][1], bh[2 * nt2 + 1][0], bh[2 * nt2 + 1][1], baseBh + ro);
                ldsm_x4(bl[2 * nt2][0], bl[2 * nt2][1], bl[2 * nt2 + 1][0], bl[2 * nt2 + 1][1], baseBl + ro);
            }
#pragma unroll
            for (int mt = 0; mt < 2; mt++)
#pragma unroll
                for (int nt = 0; nt < 8; nt++) {
                    mma16816(acc[mt][nt], ah[mt], bh[nt]);
                    mma16816(acc[mt][nt], ah[mt], bl[nt]);
                    mma16816(acc[mt][nt], al[mt], bh[nt]);
                }
        }
        __syncthreads();
    }

    // ---- epilogue from registers ----
    const int cRow = lane >> 2;
    const int cCol = 2 * (lane & 3);
#pragma unroll
    for (int mt = 0; mt < 2; mt++) {
#pragma unroll
        for (int half = 0; half < 2; half++) {
            int r = row0 + wm * 32 + mt * 16 + cRow + half * 8;
            if (r >= M) continue;
#pragma unroll
            for (int nt = 0; nt < 8; nt++) {
                int n = col0 + wn * 64 + nt * 8 + cCol;
                float v0 = acc[mt][nt][half * 2 + 0] + g_f[biasOff + n];
                float v1 = acc[mt][nt][half * 2 + 1] + g_f[biasOff + n + 1];
                if (MODE == 0) {
                    long gidx = (long)r * Nc + n;
                    *reinterpret_cast<float2*>(g_f + cOff + gidx) = make_float2(v0, v1);
                } else if (MODE == 2) {
                    v0 = gelu_tanh(v0); v1 = gelu_tanh(v1);
                    long gidx = (long)r * Nc + n;
                    __nv_bfloat162 rh = *reinterpret_cast<const __nv_bfloat162*>(g_bf + resHi + gidx);
                    __nv_bfloat162 rl = *reinterpret_cast<const __nv_bfloat162*>(g_bf + resLo + gidx);
                    v0 += __bfloat162float(rh.x) + __bfloat162float(rl.x);
                    v1 += __bfloat162float(rh.y) + __bfloat162float(rl.y);
                    *reinterpret_cast<float2*>(g_f + cOff + gidx) = make_float2(v0, v1);
                } else {  // MODE 3
                    if (n < 1024) {
                        float gv0 = gelu_tanh(v0), gv1 = gelu_tanh(v1);
                        long gidx = (long)r * 1024 + n;
                        __nv_bfloat16 h0, l0, h1, l1;
                        split_bf16(gv0, h0, l0);
                        split_bf16(gv1, h1, l1);
                        __nv_bfloat162 hh; hh.x = h0; hh.y = h1;
                        __nv_bfloat162 ll; ll.x = l0; ll.y = l1;
                        *reinterpret_cast<__nv_bfloat162*>(g_bf + oHi + gidx) = hh;
                        *reinterpret_cast<__nv_bfloat162*>(g_bf + oLo + gidx) = ll;
                    } else {
                        long gidx = (long)r * 1024 + (n - 1024);
                        *reinterpret_cast<float2*>(g_f + cOff + gidx) = make_float2(v0, v1);
                    }
                }
            }
        }
    }
}

// ===========================================================================
// all weight conversions in one kernel (transpose + split-bf16)
// ===========================================================================
__global__ void conv_all(const float* __restrict__ Wq, const float* __restrict__ Wk,
                         const float* __restrict__ Wei, const float* __restrict__ Wfi,
                         const float* __restrict__ Weh, const float* __restrict__ Wfh)
{
    long i = (long)blockIdx.x * blockDim.x + threadIdx.x;
    if (i >= 3670016L) return;
    const float* W; long o, dh, dl; int NcS, Kd;
    if (i < 262144L)       { W = Wq;  o = i;            dh = cfg::B_WQK_HI;          dl = cfg::B_WQK_LO;          NcS = 512;  Kd = 512; }
    else if (i < 524288L)  { W = Wk;  o = i - 262144L;  dh = cfg::B_WQK_HI + 262144; dl = cfg::B_WQK_LO + 262144; NcS = 512;  Kd = 512; }
    else if (i < 1048576L) { W = Wei; o = i - 524288L;  dh = cfg::B_WIN_HI;          dl = cfg::B_WIN_LO;          NcS = 1024; Kd = 512; }
    else if (i < 1572864L) { W = Wfi; o = i - 1048576L; dh = cfg::B_WIN_HI + 524288; dl = cfg::B_WIN_LO + 524288; NcS = 1024; Kd = 512; }
    else if (i < 2621440L) { W = Weh; o = i - 1572864L; dh = cfg::B_WEH_HI;          dl = cfg::B_WEH_LO;          NcS = 1024; Kd = 1024; }
    else                   { W = Wfh; o = i - 2621440L; dh = cfg::B_WFH_HI;          dl = cfg::B_WFH_LO;          NcS = 1024; Kd = 1024; }
    int n = (int)(o / Kd);
    int k = (int)(o % Kd);
    float v = W[(long)k * NcS + n];
    __nv_bfloat16 h, l;
    split_bf16(v, h, l);
    g_bf[dh + o] = h;
    g_bf[dl + o] = l;
}

// concat biases into fp32 scratch
__global__ void bias_concat(const float* __restrict__ bq, const float* __restrict__ bk,
                            const float* __restrict__ bei, const float* __restrict__ bfi,
                            const float* __restrict__ beh, const float* __restrict__ bfh)
{
    int i = blockIdx.x * blockDim.x + threadIdx.x;
    if (i < 1024) g_f[cfg::OFF_BQK + i] = (i < 512) ? bq[i] : bk[i - 512];
    else if (i < 3072) { int j = i - 1024; g_f[cfg::OFF_BIN + j] = (j < 1024) ? bei[j] : bfi[j - 1024]; }
    else if (i < 4096) g_f[cfg::OFF_BEH + i - 3072] = beh[i - 3072];
    else if (i < 5120) g_f[cfg::OFF_BFH + i - 4096] = bfh[i - 4096];
}

// ===========================================================================
__global__ void init_kernel() {
    int i = blockIdx.x * blockDim.x + threadIdx.x;
    const unsigned NEG_INF_KEY = 0x007FFFFFu;  // f2u(-inf)
    if (i < cfg::N * cfg::H) {
        g_f[cfg::OFF_DEN + i] = 0.0f;
        reinterpret_cast<unsigned*>(g_f + cfg::OFF_MXU)[i] = NEG_INF_KEY;
    }
    if (i < cfg::N * 24) {
        g_f[cfg::OFF_ATT + i] = 0.0f;
    }
}

// ===========================================================================
// double LayerNorm -> split bf16 activations
// ===========================================================================
__global__ __launch_bounds__(128) void ln_kernel(
    const float* __restrict__ x,
    const float* __restrict__ ga, const float* __restrict__ ba,
    const float* __restrict__ gm, const float* __restrict__ bm)
{
    int row = blockIdx.x;
    int t = threadIdx.x;
    const float* xr = x + (long)row * cfg::D;

    float v[4];
    float s = 0.f, ss = 0.f;
#pragma unroll
    for (int i = 0; i < 4; i++) {
        v[i] = xr[t + 128 * i];
        s += v[i];
        ss += v[i] * v[i];
    }
    __shared__ float sh[2][4];
#pragma unroll
    for (int o = 16; o > 0; o >>= 1) {
        s  += __shfl_down_sync(0xffffffffu, s, o);
        ss += __shfl_down_sync(0xffffffffu, ss, o);
    }
    if ((t & 31) == 0) { sh[0][t >> 5] = s; sh[1][t >> 5] = ss; }
    __syncthreads();
    if (t == 0) {
        float S  = sh[0][0] + sh[0][1] + sh[0][2] + sh[0][3];
        float SS = sh[1][0] + sh[1][1] + sh[1][2] + sh[1][3];
        float mean = S / cfg::D;
        float var  = SS / cfg::D - mean * mean;
        sh[0][0] = mean;
        sh[1][0] = rsqrtf(var + 1e-5f);
    }
    __syncthreads();
    float mean = sh[0][0], rstd = sh[1][0];
#pragma unroll
    for (int i = 0; i < 4; i++) {
        int c = t + 128 * i;
        float zn = (v[i] - mean) * rstd;
        float za = zn * ga[c] + ba[c];
        float zm = zn * gm[c] + bm[c];
        __nv_bfloat16 h, l;
        split_bf16(za, h, l);
        g_bf[cfg::B_ZATT_HI + (long)row * cfg::D + c] = h;
        g_bf[cfg::B_ZATT_LO + (long)row * cfg::D + c] = l;
        split_bf16(zm, h, l);
        g_bf[cfg::B_ZMLP_HI + (long)row * cfg::D + c] = h;
        g_bf[cfg::B_ZMLP_LO + (long)row * cfg::D + c] = l;
    }
}

// ===========================================================================
// edge attention
// ===========================================================================
__global__ __launch_bounds__(256) void edge_logits_kernel(
    const int* __restrict__ ei, const float* __restrict__ att_bias)
{
    long gtid = (long)blockIdx.x * blockDim.x + threadIdx.x;
    long e = gtid >> 5;
    if (e >= cfg::E) return;
    int lane = threadIdx.x & 31;
    int r = ei[e];
    int c = ei[cfg::E + e];

    const float4* qr = reinterpret_cast<const float4*>(g_f + cfg::OFF_QK + (long)r * 1024) + lane * 4;
    const float4* kr = reinterpret_cast<const float4*>(g_f + cfg::OFF_QK + (long)c * 1024 + 512) + lane * 4;
    float s = 0.f;
#pragma unroll
    for (int i = 0; i < 4; i++) {
        float4 a = qr[i], b = kr[i];
        s += a.x * b.x + a.y * b.y + a.z * b.z + a.w * b.w;
    }
    s += __shfl_xor_sync(0xffffffffu, s, 1);
    s += __shfl_xor_sync(0xffffffffu, s, 2);
    if ((lane & 3) == 0) {
        int h = lane >> 2;
        float lg = s * 0.125f + att_bias[e];
        g_f[cfg::OFF_LOG + e * cfg::H + h] = lg;
        atomicMax(&reinterpret_cast<unsigned*>(g_f + cfg::OFF_MXU)[r * cfg::H + h], f2u(lg));
    }
}

__global__ void finalize_mx_kernel() {
    int i = blockIdx.x * blockDim.x + threadIdx.x;
    if (i >= cfg::N * cfg::H) return;
    float v = u2f(reinterpret_cast<unsigned*>(g_f + cfg::OFF_MXU)[i]);
    g_f[cfg::OFF_MX + i] = isfinite(v) ? v : 0.0f;
}

// merged: p = exp(lg - mx); den += p; att_sum += p*pos  (unnormalized)
__global__ __launch_bounds__(256) void edge_exp_contrib_kernel(
    const int* __restrict__ ei, const float* __restrict__ pos)
{
    long e = (long)blockIdx.x * blockDim.x + threadIdx.x;
    if (e >= cfg::E) return;
    int r = ei[e];
    int c = ei[cfg::E + e];
    float px = pos[(long)c * 3 + 0];
    float py = pos[(long)c * 3 + 1];
    float pz = pos[(long)c * 3 + 2];
#pragma unroll
    for (int h = 0; h < cfg::H; h++) {
        float p = expf(g_f[cfg::OFF_LOG + e * cfg::H + h] - g_f[cfg::OFF_MX + r * cfg::H + h]);
        atomicAdd(&g_f[cfg::OFF_DEN + r * cfg::H + h], p);
        atomicAdd(&g_f[cfg::OFF_ATT + (long)r * 24 + h * 3 + 0], p * px);
        atomicAdd(&g_f[cfg::OFF_ATT + (long)r * 24 + h * 3 + 1], p * py);
        atomicAdd(&g_f[cfg::OFF_ATT + (long)r * 24 + h * 3 + 2], p * pz);
    }
}

// ===========================================================================
// forces h1 fixup: h1f = gelu(raw + attminus @ W24) -> split bf16
// 16 rows per block; W24 (24x1024) cached in smem
// ===========================================================================
constexpr int FIX_SMEM = (24 * 1025 + 16 * 24) * 4;   // ~99.9 KB

__global__ __launch_bounds__(256) void forces_h1_kernel(
    const float* __restrict__ Wfi, const float* __restrict__ pos)
{
    extern __shared__ float sw[];
    float* w24 = sw;                 // [24][1025]
    float* am  = sw + 24 * 1025;     // [16][24]
    int n0 = blockIdx.x * 16;
    int t = threadIdx.x;

    for (int idx = t; idx < 24 * 1024; idx += 256) {
        int k = idx >> 10, j = idx & 1023;
        w24[k * 1025 + j] = Wfi[(long)(512 + k) * 1024 + j];
    }
    for (int idx = t; idx < 16 * 24; idx += 256) {
        int i = idx / 24, k = idx % 24;
        int n = n0 + i;
        int h = k / 3, ax = k % 3;
        float d = g_f[cfg::OFF_DEN + (long)n * 8 + h];
        float a = (d > 0.f) ? g_f[cfg::OFF_ATT + (long)n * 24 + k] / d : 0.f;
        am[idx] = a - pos[(long)n * 3 + ax];
    }
    __syncthreads();

#pragma unroll
    for (int jj = 0; jj < 4; jj++) {
        int j = t + jj * 256;
        float w[24];
#pragma unroll
        for (int k = 0; k < 24; k++) w[k] = w24[k * 1025 + j];
        for (int i = 0; i < 16; i++) {
            long gi = (long)(n0 + i) * 1024 + j;
            float v = g_f[cfg::OFF_RAWF + gi];
#pragma unroll
            for (int k = 0; k < 24; k++) v = fmaf(am[i * 24 + k], w[k], v);
            v = gelu_tanh(v);
            __nv_bfloat16 hh, ll;
            split_bf16(v, hh, ll);
            g_bf[cfg::B_H1F_HI + gi] = hh;
            g_bf[cfg::B_H1F_LO + gi] = ll;
        }
    }
}

// ===========================================================================
// fused output heads: energy [1024->1], forces [1024->3]
// ===========================================================================
__global__ __launch_bounds__(256) void heads_kernel(
    const float* __restrict__ Weo, const float* __restrict__ beo,
    const float* __restrict__ Wfo, const float* __restrict__ bfo,
    float* __restrict__ out)
{
    int n = blockIdx.x;
    int t = threadIdx.x;
    const float* he = g_f + cfg::OFF_H2E + (long)n * 1024;
    const float* hf = g_f + cfg::OFF_H2F + (long)n * 1024;
    float s = 0.f, s0 = 0.f, s1 = 0.f, s2 = 0.f;
    for (int j = t; j < 1024; j += 256) {
        s += he[j] * Weo[j];
        float hv = hf[j];
        s0 += hv * Wfo[j * 3 + 0];
        s1 += hv * Wfo[j * 3 + 1];
        s2 += hv * Wfo[j * 3 + 2];
    }
    __shared__ float sh[4][8];
#pragma unroll
    for (int o = 16; o > 0; o >>= 1) {
        s  += __shfl_down_sync(0xffffffffu, s,  o);
        s0 += __shfl_down_sync(0xffffffffu, s0, o);
        s1 += __shfl_down_sync(0xffffffffu, s1, o);
        s2 += __shfl_down_sync(0xffffffffu, s2, o);
    }
    if ((t & 31) == 0) {
        int w = t >> 5;
        sh[0][w] = s; sh[1][w] = s0; sh[2][w] = s1; sh[3][w] = s2;
    }
    __syncthreads();
    if (t == 0) {
        float t0 = 0.f, t1 = 0.f, t2 = 0.f, t3 = 0.f;
#pragma unroll
        for (int i = 0; i < 8; i++) { t0 += sh[0][i]; t1 += sh[1][i]; t2 += sh[2][i]; t3 += sh[3][i]; }
        out[n] = t0 + beo[0];
        out[(long)cfg::N + (long)n * 3 + 0] = t1 + bfo[0];
        out[(long)cfg::N + (long)n * 3 + 1] = t2 + bfo[1];
        out[(long)cfg::N + (long)n * 3 + 2] = t3 + bfo[2];
    }
}

// ===========================================================================
extern "C" void kernel_launch(void* const* d_in, const int* in_sizes, int n_in,
                              void* d_out, int out_size)
{
    const float* x        = (const float*)d_in[0];
    const int*   ei       = (const int*)  d_in[1];
    const float* att_bias = (const float*)d_in[2];
    const float* pos      = (const float*)d_in[3];
    const float* g_att  = (const float*)d_in[5];
    const float* b_att  = (const float*)d_in[6];
    const float* g_mlp  = (const float*)d_in[7];
    const float* b_mlp  = (const float*)d_in[8];
    const float* Wq     = (const float*)d_in[9];
    const float* bq     = (const float*)d_in[10];
    const float* Wk     = (const float*)d_in[11];
    const float* bk     = (const float*)d_in[12];
    const float* We_in  = (const float*)d_in[13];
    const float* be_in  = (const float*)d_in[14];
    const float* We_h   = (const float*)d_in[15];
    const float* be_h   = (const float*)d_in[16];
    const float* We_out = (const float*)d_in[17];
    const float* be_out = (const float*)d_in[18];
    const float* Wf_in  = (const float*)d_in[19];
    const float* bf_in  = (const float*)d_in[20];
    const float* Wf_h   = (const float*)d_in[21];
    const float* bf_h   = (const float*)d_in[22];
    const float* Wf_out = (const float*)d_in[23];
    const float* bf_out = (const float*)d_in[24];
    float* out = (float*)d_out;

    cudaFuncSetAttribute(tc_gemm<0>, cudaFuncAttributeMaxDynamicSharedMemorySize, GEMM_SMEM);
    cudaFuncSetAttribute(tc_gemm<2>, cudaFuncAttributeMaxDynamicSharedMemorySize, GEMM_SMEM);
    cudaFuncSetAttribute(tc_gemm<3>, cudaFuncAttributeMaxDynamicSharedMemorySize, GEMM_SMEM);
    cudaFuncSetAttribute(forces_h1_kernel, cudaFuncAttributeMaxDynamicSharedMemorySize, FIX_SMEM);

    const int MB = (cfg::N + 127) / 128;   // 157

    // launch 0: init
    init_kernel<<<(cfg::N * 24 + 255) / 256, 256>>>();
    // launch 1: LN
    ln_kernel<<<cfg::N, 128>>>(x, g_att, b_att, g_mlp, b_mlp);
    // launch 2: bias concat
    bias_concat<<<20, 256>>>(bq, bk, be_in, bf_in, be_h, bf_h);
    // launch 3: all weight conversions
    conv_all<<<(unsigned)((3670016L + 255) / 256), 256>>>(Wq, Wk, We_in, Wf_in, We_h, Wf_h);
    // launch 4: fused QK projection  [N,1024]
    tc_gemm<0><<<dim3(8, MB), 256, GEMM_SMEM>>>(cfg::B_ZATT_HI, cfg::B_ZATT_LO,
        cfg::B_WQK_HI, cfg::B_WQK_LO, cfg::OFF_BQK, 0, 0, cfg::OFF_QK, 0, 0,
        cfg::N, 1024, 512);
    // launch 5 (ncu-captured): edge logits
    long logit_threads = (long)cfg::E * 32;
    edge_logits_kernel<<<(unsigned)((logit_threads + 255) / 256), 256>>>(ei, att_bias);
    // launch 6
    finalize_mx_kernel<<<(cfg::N * cfg::H + 255) / 256, 256>>>();
    // launch 7: merged exp+contrib (unnormalized)
    edge_exp_contrib_kernel<<<(cfg::E + 255) / 256, 256>>>(ei, pos);
    // launch 8: fused in-projection [N,2048] over z_mlp
    tc_gemm<3><<<dim3(16, MB), 256, GEMM_SMEM>>>(cfg::B_ZMLP_HI, cfg::B_ZMLP_LO,
        cfg::B_WIN_HI, cfg::B_WIN_LO, cfg::OFF_BIN, 0, 0, cfg::OFF_RAWF,
        cfg::B_H1E_HI, cfg::B_H1E_LO, cfg::N, 2048, 512);
    // launch 9: forces h1 fixup (att part + gelu + split)
    forces_h1_kernel<<<cfg::N / 16, 256, FIX_SMEM>>>(Wf_in, pos);
    // launch 10: energy hidden block
    tc_gemm<2><<<dim3(8, MB), 256, GEMM_SMEM>>>(cfg::B_H1E_HI, cfg::B_H1E_LO,
        cfg::B_WEH_HI, cfg::B_WEH_LO, cfg::OFF_BEH,
        cfg::B_H1E_HI, cfg::B_H1E_LO, cfg::OFF_H2E, 0, 0, cfg::N, 1024, 1024);
    // launch 11: forces hidden block
    tc_gemm<2><<<dim3(8, MB), 256, GEMM_SMEM>>>(cfg::B_H1F_HI, cfg::B_H1F_LO,
        cfg::B_WFH_HI, cfg::B_WFH_LO, cfg::OFF_BFH,
        cfg::B_H1F_HI, cfg::B_H1F_LO, cfg::OFF_H2F, 0, 0, cfg::N, 1024, 1024);
    // launch 12: fused output heads
    heads_kernel<<<cfg::N, 256>>>(We_out, be_out, Wf_out, bf_out, out);
}

// round 5
// speedup vs baseline: 1.0988x; 1.0988x over previous
#include <cuda_runtime.h>
#include <cuda_bf16.h>
#include <math.h>
#include <stdint.h>

#define DEV_INLINE __device__ __forceinline__

namespace cfg {
constexpr int N = 20000;
constexpr int E = 600000;
constexpr int D = 512;
constexpr int H = 8;
constexpr int HID = 1024;

// ---- fp32 scratch offsets ----
constexpr long OFF_QK   = 0;                          // N*1024 (q | k)
constexpr long OFF_CB   = OFF_QK  + (long)N * 1024;   // E (csr-permuted att_bias)
constexpr long OFF_ATT  = OFF_CB  + (long)E;          // N*24 (att/den - pos, "attminus")
constexpr long OFF_RAWF = OFF_ATT + (long)N * 24;     // N*1024 (pre-gelu forces h1, partial)
constexpr long OFF_H2E  = OFF_RAWF+ (long)N * 1024;   // N*1024
constexpr long OFF_H2F  = OFF_H2E + (long)N * 1024;   // N*1024
constexpr long OFF_BQK  = OFF_H2F + (long)N * 1024;   // 1024
constexpr long OFF_BIN  = OFF_BQK + 1024;             // 2048
constexpr long OFF_BEH  = OFF_BIN + 2048;             // 1024
constexpr long OFF_BFH  = OFF_BEH + 1024;             // 1024
constexpr long FTOTAL   = OFF_BFH + 1024;

// ---- int scratch ----
constexpr long I_ROWPTR = 0;            // N+1
constexpr long I_WOFS   = N + 1;        // N+1  (counts, then write cursors)
constexpr long I_COL    = 2 * (N + 1);  // E
constexpr long ITOTAL   = I_COL + E;

// ---- bf16 scratch offsets ----
constexpr long B_ZATT_HI = 0;
constexpr long B_ZATT_LO = B_ZATT_HI + (long)N * D;
constexpr long B_ZMLP_HI = B_ZATT_LO + (long)N * D;
constexpr long B_ZMLP_LO = B_ZMLP_HI + (long)N * D;
constexpr long B_H1E_HI  = B_ZMLP_LO + (long)N * D;
constexpr long B_H1E_LO  = B_H1E_HI  + (long)N * HID;
constexpr long B_H1F_HI  = B_H1E_LO  + (long)N * HID;
constexpr long B_H1F_LO  = B_H1F_HI  + (long)N * HID;
constexpr long B_WQK_HI  = B_H1F_LO  + (long)N * HID;   // [1024, 512]
constexpr long B_WQK_LO  = B_WQK_HI  + 1024L * 512;
constexpr long B_WIN_HI  = B_WQK_LO  + 1024L * 512;     // [2048, 512]
constexpr long B_WIN_LO  = B_WIN_HI  + 2048L * 512;
constexpr long B_WEH_HI  = B_WIN_LO  + 2048L * 512;     // [1024, 1024]
constexpr long B_WEH_LO  = B_WEH_HI  + 1024L * 1024;
constexpr long B_WFH_HI  = B_WEH_LO  + 1024L * 1024;
constexpr long B_WFH_LO  = B_WFH_HI  + 1024L * 1024;
constexpr long BTOTAL    = B_WFH_LO  + 1024L * 1024;
}

__device__ float g_f[cfg::FTOTAL];
__device__ int   g_i[cfg::ITOTAL];
__device__ __nv_bfloat16 g_bf[cfg::BTOTAL];

// ===========================================================================
// helpers
// ===========================================================================
DEV_INLINE float gelu_tanh(float x) {
    float x3 = x * x * x;
    float t = tanhf(0.7978845608028654f * (x + 0.044715f * x3));
    return 0.5f * x * (1.0f + t);
}
DEV_INLINE void split_bf16(float v, __nv_bfloat16& h, __nv_bfloat16& l) {
    h = __float2bfloat16(v);
    l = __float2bfloat16(v - __bfloat162float(h));
}
DEV_INLINE uint32_t smem_u32(const void* p) {
    uint32_t a;
    asm("{ .reg .u64 t; cvta.to.shared.u64 t, %1; cvt.u32.u64 %0, t; }" : "=r"(a) : "l"(p));
    return a;
}
DEV_INLINE void cp16(uint32_t dst, const void* src, int szbytes) {
    asm volatile("cp.async.cg.shared.global [%0], [%1], 16, %2;\n" :: "r"(dst), "l"(src), "r"(szbytes));
}
DEV_INLINE void cp_commit() { asm volatile("cp.async.commit_group;\n"); }
template <int NN>
DEV_INLINE void cp_wait() { asm volatile("cp.async.wait_group %0;\n" :: "n"(NN) : "memory"); }

DEV_INLINE void ldsm_x4(uint32_t& r0, uint32_t& r1, uint32_t& r2, uint32_t& r3, uint32_t addr) {
    asm volatile("ldmatrix.sync.aligned.m8n8.x4.shared.b16 {%0,%1,%2,%3}, [%4];"
                 : "=r"(r0), "=r"(r1), "=r"(r2), "=r"(r3) : "r"(addr));
}
DEV_INLINE void mma16816(float* c, const uint32_t* a, const uint32_t* b) {
    asm volatile("mma.sync.aligned.m16n8k16.row.col.f32.bf16.bf16.f32 "
                 "{%0,%1,%2,%3}, {%4,%5,%6,%7}, {%8,%9}, {%0,%1,%2,%3};"
                 : "+f"(c[0]), "+f"(c[1]), "+f"(c[2]), "+f"(c[3])
                 : "r"(a[0]), "r"(a[1]), "r"(a[2]), "r"(a[3]), "r"(b[0]), "r"(b[1]));
}

// ===========================================================================
// split-bf16 HMMA GEMM (3-term compensation) — unchanged proven core
// MODE 0: C fp32 = acc + bias
// MODE 2: C fp32 = (resHi+resLo) + gelu(acc+bias)
// MODE 3: col<1024: gelu+split-bf16 -> oHi/oLo ; col>=1024: raw fp32 -> cOff
// ===========================================================================
constexpr int PADK = 40;
constexpr int MAT_BYTES = 128 * PADK * 2;
constexpr int STG_BYTES = 4 * MAT_BYTES;
constexpr int GEMM_SMEM = 2 * STG_BYTES;

template <int MODE>
__global__ __launch_bounds__(256) void tc_gemm(
    long aHi, long aLo, long bHi, long bLo, long biasOff,
    long resHi, long resLo, long cOff, long oHi, long oLo,
    int M, int Nc, int K)
{
    extern __shared__ char smem[];
    const uint32_t sb = smem_u32(smem);
    const int tid = threadIdx.x;
    const int wid = tid >> 5;
    const int lane = tid & 31;
    const int row0 = blockIdx.y * 128;
    const int col0 = blockIdx.x * 128;
    const int wm = wid & 3;
    const int wn = wid >> 2;

    const __nv_bfloat16* Ah = g_bf + aHi;
    const __nv_bfloat16* Al = g_bf + aLo;
    const __nv_bfloat16* Bh = g_bf + bHi;
    const __nv_bfloat16* Bl = g_bf + bLo;

    const int nChunks = K >> 5;

    auto load_stage = [&](int stage, int chunk) {
        const long k0 = (long)chunk << 5;
        const uint32_t base = sb + stage * STG_BYTES;
#pragma unroll
        for (int j = 0; j < 2; j++) {
            int i = tid + j * 256;
            int r = i >> 2;
            int seg = i & 3;
            uint32_t so = r * 80 + seg * 16;
            bool va = (row0 + r) < M;
            long ar = va ? (long)(row0 + r) : 0;
            cp16(base + so,                 Ah + ar * K + k0 + seg * 8, va ? 16 : 0);
            cp16(base + MAT_BYTES + so,     Al + ar * K + k0 + seg * 8, va ? 16 : 0);
            long br = (long)(col0 + r);
            cp16(base + 2 * MAT_BYTES + so, Bh + br * K + k0 + seg * 8, 16);
            cp16(base + 3 * MAT_BYTES + so, Bl + br * K + k0 + seg * 8, 16);
        }
    };

    float acc[2][8][4];
#pragma unroll
    for (int mt = 0; mt < 2; mt++)
#pragma unroll
        for (int nt = 0; nt < 8; nt++)
#pragma unroll
            for (int q = 0; q < 4; q++) acc[mt][nt][q] = 0.f;

    const int aRowOff = (lane & 7) + 8 * ((lane >> 3) & 1);
    const int aKbyte  = 16 * (lane >> 4);
    const int bRowOff = (lane & 7) + 8 * (lane >> 4);
    const int bKbyte  = 16 * ((lane >> 3) & 1);

    load_stage(0, 0);
    cp_commit();

    for (int c = 0; c < nChunks; c++) {
        if (c + 1 < nChunks) {
            load_stage((c + 1) & 1, c + 1);
            cp_commit();
            cp_wait<1>();
        } else {
            cp_wait<0>();
        }
        __syncthreads();

        const uint32_t st = sb + (c & 1) * STG_BYTES;
        const uint32_t baseAh = st;
        const uint32_t baseAl = st + MAT_BYTES;
        const uint32_t baseBh = st + 2 * MAT_BYTES;
        const uint32_t baseBl = st + 3 * MAT_BYTES;

#pragma unroll
        for (int kt = 0; kt < 2; kt++) {
            const int kb = kt * 32;
            uint32_t ah[2][4], al[2][4];
#pragma unroll
            for (int mt = 0; mt < 2; mt++) {
                uint32_t ro = (wm * 32 + mt * 16 + aRowOff) * 80 + kb + aKbyte;
                ldsm_x4(ah[mt][0], ah[mt][1], ah[mt][2], ah[mt][3], baseAh + ro);
                ldsm_x4(al[mt][0], al[mt][1], al[mt][2], al[mt][3], baseAl + ro);
            }
            uint32_t bh[8][2], bl[8][2];
#pragma unroll
            for (int nt2 = 0; nt2 < 4; nt2++) {
                uint32_t ro = (wn * 64 + nt2 * 16 + bRowOff) * 80 + kb + bKbyte;
                ldsm_x4(bh[2 * nt2][0], bh[2 * nt2][1], bh[2 * nt2 + 1][0], bh[2 * nt2 + 1][1], baseBh + ro);
                ldsm_x4(bl[2 * nt2][0], bl[2 * nt2][1], bl[2 * nt2 + 1][0], bl[2 * nt2 + 1][1], baseBl + ro);
            }
#pragma unroll
            for (int mt = 0; mt < 2; mt++)
#pragma unroll
                for (int nt = 0; nt < 8; nt++) {
                    mma16816(acc[mt][nt], ah[mt], bh[nt]);
                    mma16816(acc[mt][nt], ah[mt], bl[nt]);
                    mma16816(acc[mt][nt], al[mt], bh[nt]);
                }
        }
        __syncthreads();
    }

    const int cRow = lane >> 2;
    const int cCol = 2 * (lane & 3);
#pragma unroll
    for (int mt = 0; mt < 2; mt++) {
#pragma unroll
        for (int half = 0; half < 2; half++) {
            int r = row0 + wm * 32 + mt * 16 + cRow + half * 8;
            if (r >= M) continue;
#pragma unroll
            for (int nt = 0; nt < 8; nt++) {
                int n = col0 + wn * 64 + nt * 8 + cCol;
                float v0 = acc[mt][nt][half * 2 + 0] + g_f[biasOff + n];
                float v1 = acc[mt][nt][half * 2 + 1] + g_f[biasOff + n + 1];
                if (MODE == 0) {
                    long gidx = (long)r * Nc + n;
                    *reinterpret_cast<float2*>(g_f + cOff + gidx) = make_float2(v0, v1);
                } else if (MODE == 2) {
                    v0 = gelu_tanh(v0); v1 = gelu_tanh(v1);
                    long gidx = (long)r * Nc + n;
                    __nv_bfloat162 rh = *reinterpret_cast<const __nv_bfloat162*>(g_bf + resHi + gidx);
                    __nv_bfloat162 rl = *reinterpret_cast<const __nv_bfloat162*>(g_bf + resLo + gidx);
                    v0 += __bfloat162float(rh.x) + __bfloat162float(rl.x);
                    v1 += __bfloat162float(rh.y) + __bfloat162float(rl.y);
                    *reinterpret_cast<float2*>(g_f + cOff + gidx) = make_float2(v0, v1);
                } else {  // MODE 3
                    if (n < 1024) {
                        float gv0 = gelu_tanh(v0), gv1 = gelu_tanh(v1);
                        long gidx = (long)r * 1024 + n;
                        __nv_bfloat16 h0, l0, h1, l1;
                        split_bf16(gv0, h0, l0);
                        split_bf16(gv1, h1, l1);
                        __nv_bfloat162 hh; hh.x = h0; hh.y = h1;
                        __nv_bfloat162 ll; ll.x = l0; ll.y = l1;
                        *reinterpret_cast<__nv_bfloat162*>(g_bf + oHi + gidx) = hh;
                        *reinterpret_cast<__nv_bfloat162*>(g_bf + oLo + gidx) = ll;
                    } else {
                        long gidx = (long)r * 1024 + (n - 1024);
                        *reinterpret_cast<float2*>(g_f + cOff + gidx) = make_float2(v0, v1);
                    }
                }
            }
        }
    }
}

// ===========================================================================
// weight conversion (transpose + split-bf16), all weights in one kernel
// ===========================================================================
__global__ void conv_all(const float* __restrict__ Wq, const float* __restrict__ Wk,
                         const float* __restrict__ Wei, const float* __restrict__ Wfi,
                         const float* __restrict__ Weh, const float* __restrict__ Wfh)
{
    long i = (long)blockIdx.x * blockDim.x + threadIdx.x;
    if (i >= 3670016L) return;
    const float* W; long o, dh, dl; int NcS, Kd;
    if (i < 262144L)       { W = Wq;  o = i;            dh = cfg::B_WQK_HI;          dl = cfg::B_WQK_LO;          NcS = 512;  Kd = 512; }
    else if (i < 524288L)  { W = Wk;  o = i - 262144L;  dh = cfg::B_WQK_HI + 262144; dl = cfg::B_WQK_LO + 262144; NcS = 512;  Kd = 512; }
    else if (i < 1048576L) { W = Wei; o = i - 524288L;  dh = cfg::B_WIN_HI;          dl = cfg::B_WIN_LO;          NcS = 1024; Kd = 512; }
    else if (i < 1572864L) { W = Wfi; o = i - 1048576L; dh = cfg::B_WIN_HI + 524288; dl = cfg::B_WIN_LO + 524288; NcS = 1024; Kd = 512; }
    else if (i < 2621440L) { W = Weh; o = i - 1572864L; dh = cfg::B_WEH_HI;          dl = cfg::B_WEH_LO;          NcS = 1024; Kd = 1024; }
    else                   { W = Wfh; o = i - 2621440L; dh = cfg::B_WFH_HI;          dl = cfg::B_WFH_LO;          NcS = 1024; Kd = 1024; }
    int n = (int)(o / Kd);
    int k = (int)(o % Kd);
    float v = W[(long)k * NcS + n];
    __nv_bfloat16 h, l;
    split_bf16(v, h, l);
    g_bf[dh + o] = h;
    g_bf[dl + o] = l;
}

__global__ void bias_concat(const float* __restrict__ bq, const float* __restrict__ bk,
                            const float* __restrict__ bei, const float* __restrict__ bfi,
                            const float* __restrict__ beh, const float* __restrict__ bfh)
{
    int i = blockIdx.x * blockDim.x + threadIdx.x;
    if (i < 1024) g_f[cfg::OFF_BQK + i] = (i < 512) ? bq[i] : bk[i - 512];
    else if (i < 3072) { int j = i - 1024; g_f[cfg::OFF_BIN + j] = (j < 1024) ? bei[j] : bfi[j - 1024]; }
    else if (i < 4096) g_f[cfg::OFF_BEH + i - 3072] = beh[i - 3072];
    else if (i < 5120) g_f[cfg::OFF_BFH + i - 4096] = bfh[i - 4096];
}

// ===========================================================================
// CSR build
// ===========================================================================
__global__ void csr_zero() {
    int i = blockIdx.x * blockDim.x + threadIdx.x;
    if (i <= cfg::N) g_i[cfg::I_WOFS + i] = 0;
}
__global__ void csr_count(const int* __restrict__ ei) {
    int e = blockIdx.x * blockDim.x + threadIdx.x;
    if (e < cfg::E) atomicAdd(&g_i[cfg::I_WOFS + ei[e]], 1);
}
// single block of 1024 threads, each covering 20 nodes
__global__ __launch_bounds__(1024) void csr_scan() {
    __shared__ int sh[1024];
    int t = threadIdx.x;
    int loc[20];
    int base = t * 20;
    int sum = 0;
#pragma unroll
    for (int j = 0; j < 20; j++) {
        int idx = base + j;
        int v = (idx < cfg::N) ? g_i[cfg::I_WOFS + idx] : 0;
        loc[j] = sum;
        sum += v;
    }
    sh[t] = sum;
    __syncthreads();
    // Hillis-Steele inclusive scan on sh
    for (int off = 1; off < 1024; off <<= 1) {
        int v = (t >= off) ? sh[t - off] : 0;
        __syncthreads();
        sh[t] += v;
        __syncthreads();
    }
    int pre = (t == 0) ? 0 : sh[t - 1];
#pragma unroll
    for (int j = 0; j < 20; j++) {
        int idx = base + j;
        if (idx < cfg::N) {
            g_i[cfg::I_ROWPTR + idx] = pre + loc[j];
            g_i[cfg::I_WOFS + idx]   = pre + loc[j];
        }
    }
    if (t == 0) g_i[cfg::I_ROWPTR + cfg::N] = cfg::E;
}
__global__ void csr_scatter(const int* __restrict__ ei, const float* __restrict__ att_bias) {
    int e = blockIdx.x * blockDim.x + threadIdx.x;
    if (e >= cfg::E) return;
    int r = ei[e];
    int p = atomicAdd(&g_i[cfg::I_WOFS + r], 1);
    g_i[cfg::I_COL + p] = ei[cfg::E + e];
    g_f[cfg::OFF_CB + p] = att_bias[e];
}

// ===========================================================================
// one-pass edge attention: warp per node, online softmax + position average
// writes attminus[n,24] = att/den - pos[n]
// ===========================================================================
__global__ __launch_bounds__(256) void edge_attn_kernel(const float* __restrict__ pos) {
    int n = blockIdx.x * 8 + (threadIdx.x >> 5);
    if (n >= cfg::N) return;
    int lane = threadIdx.x & 31;

    int base = g_i[cfg::I_ROWPTR + n];
    int deg  = g_i[cfg::I_ROWPTR + n + 1] - base;

    // q row: lane covers 16 elems (head = lane/4)
    const float4* qr = reinterpret_cast<const float4*>(g_f + cfg::OFF_QK + (long)n * 1024) + lane * 4;
    float4 q0 = qr[0], q1 = qr[1], q2 = qr[2], q3 = qr[3];

    // this node's pos (broadcast)
    float prv = (lane < 3) ? pos[(long)n * 3 + lane] : 0.f;
    float prx = __shfl_sync(0xffffffffu, prv, 0);
    float pry = __shfl_sync(0xffffffffu, prv, 1);
    float prz = __shfl_sync(0xffffffffu, prv, 2);

    float m = -1e30f, d = 0.f, a0 = 0.f, a1 = 0.f, a2 = 0.f;

    for (int i = 0; i < deg; i++) {
        int c = g_i[cfg::I_COL + base + i];
        float bias = g_f[cfg::OFF_CB + base + i];
        const float4* kr = reinterpret_cast<const float4*>(g_f + cfg::OFF_QK + (long)c * 1024 + 512) + lane * 4;
        float4 k0 = kr[0], k1 = kr[1], k2 = kr[2], k3 = kr[3];
        float s = q0.x*k0.x + q0.y*k0.y + q0.z*k0.z + q0.w*k0.w
                + q1.x*k1.x + q1.y*k1.y + q1.z*k1.z + q1.w*k1.w
                + q2.x*k2.x + q2.y*k2.y + q2.z*k2.z + q2.w*k2.w
                + q3.x*k3.x + q3.y*k3.y + q3.z*k3.z + q3.w*k3.w;
        s += __shfl_xor_sync(0xffffffffu, s, 1);
        s += __shfl_xor_sync(0xffffffffu, s, 2);   // all 4 lanes of a head group now hold head sum

        float pv = (lane < 3) ? pos[(long)c * 3 + lane] : 0.f;
        float px = __shfl_sync(0xffffffffu, pv, 0);
        float py = __shfl_sync(0xffffffffu, pv, 1);
        float pz = __shfl_sync(0xffffffffu, pv, 2);

        float lg = s * 0.125f + bias;
        float nm = fmaxf(m, lg);
        float sc = expf(m - nm);       // 0 on first iteration (m=-1e30)
        float p  = expf(lg - nm);
        d  = d  * sc + p;
        a0 = a0 * sc + p * px;
        a1 = a1 * sc + p * py;
        a2 = a2 * sc + p * pz;
        m = nm;
    }

    if ((lane & 3) == 0) {
        int h = lane >> 2;
        float inv = (d > 0.f) ? 1.0f / d : 0.f;
        long o = (long)n * 24 + h * 3;
        g_f[cfg::OFF_ATT + o + 0] = a0 * inv - prx;
        g_f[cfg::OFF_ATT + o + 1] = a1 * inv - pry;
        g_f[cfg::OFF_ATT + o + 2] = a2 * inv - prz;
    }
}

// ===========================================================================
// forces h1 fixup: h1f = gelu(raw + attminus @ W24) -> split bf16
// ===========================================================================
constexpr int FIX_SMEM = (24 * 1025 + 16 * 24) * 4;

__global__ __launch_bounds__(256) void forces_h1_kernel(const float* __restrict__ Wfi) {
    extern __shared__ float sw[];
    float* w24 = sw;                 // [24][1025]
    float* am  = sw + 24 * 1025;     // [16][24]
    int n0 = blockIdx.x * 16;
    int t = threadIdx.x;

    for (int idx = t; idx < 24 * 1024; idx += 256) {
        int k = idx >> 10, j = idx & 1023;
        w24[k * 1025 + j] = Wfi[(long)(512 + k) * 1024 + j];
    }
    for (int idx = t; idx < 16 * 24; idx += 256) {
        int i = idx / 24, k = idx % 24;
        am[idx] = g_f[cfg::OFF_ATT + (long)(n0 + i) * 24 + k];
    }
    __syncthreads();

#pragma unroll
    for (int jj = 0; jj < 4; jj++) {
        int j = t + jj * 256;
        float w[24];
#pragma unroll
        for (int k = 0; k < 24; k++) w[k] = w24[k * 1025 + j];
        for (int i = 0; i < 16; i++) {
            long gi = (long)(n0 + i) * 1024 + j;
            float v = g_f[cfg::OFF_RAWF + gi];
#pragma unroll
            for (int k = 0; k < 24; k++) v = fmaf(am[i * 24 + k], w[k], v);
            v = gelu_tanh(v);
            __nv_bfloat16 hh, ll;
            split_bf16(v, hh, ll);
            g_bf[cfg::B_H1F_HI + gi] = hh;
            g_bf[cfg::B_H1F_LO + gi] = ll;
        }
    }
}

// ===========================================================================
// double LayerNorm -> split bf16 activations
// ===========================================================================
__global__ __launch_bounds__(128) void ln_kernel(
    const float* __restrict__ x,
    const float* __restrict__ ga, const float* __restrict__ ba,
    const float* __restrict__ gm, const float* __restrict__ bm)
{
    int row = blockIdx.x;
    int t = threadIdx.x;
    const float* xr = x + (long)row * cfg::D;

    float v[4];
    float s = 0.f, ss = 0.f;
#pragma unroll
    for (int i = 0; i < 4; i++) {
        v[i] = xr[t + 128 * i];
        s += v[i];
        ss += v[i] * v[i];
    }
    __shared__ float sh[2][4];
#pragma unroll
    for (int o = 16; o > 0; o >>= 1) {
        s  += __shfl_down_sync(0xffffffffu, s, o);
        ss += __shfl_down_sync(0xffffffffu, ss, o);
    }
    if ((t & 31) == 0) { sh[0][t >> 5] = s; sh[1][t >> 5] = ss; }
    __syncthreads();
    if (t == 0) {
        float S  = sh[0][0] + sh[0][1] + sh[0][2] + sh[0][3];
        float SS = sh[1][0] + sh[1][1] + sh[1][2] + sh[1][3];
        float mean = S / cfg::D;
        float var  = SS / cfg::D - mean * mean;
        sh[0][0] = mean;
        sh[1][0] = rsqrtf(var + 1e-5f);
    }
    __syncthreads();
    float mean = sh[0][0], rstd = sh[1][0];
#pragma unroll
    for (int i = 0; i < 4; i++) {
        int c = t + 128 * i;
        float zn = (v[i] - mean) * rstd;
        float za = zn * ga[c] + ba[c];
        float zm = zn * gm[c] + bm[c];
        __nv_bfloat16 h, l;
        split_bf16(za, h, l);
        g_bf[cfg::B_ZATT_HI + (long)row * cfg::D + c] = h;
        g_bf[cfg::B_ZATT_LO + (long)row * cfg::D + c] = l;
        split_bf16(zm, h, l);
        g_bf[cfg::B_ZMLP_HI + (long)row * cfg::D + c] = h;
        g_bf[cfg::B_ZMLP_LO + (long)row * cfg::D + c] = l;
    }
}

// ===========================================================================
// fused output heads
// ===========================================================================
__global__ __launch_bounds__(256) void heads_kernel(
    const float* __restrict__ Weo, const float* __restrict__ beo,
    const float* __restrict__ Wfo, const float* __restrict__ bfo,
    float* __restrict__ out)
{
    int n = blockIdx.x;
    int t = threadIdx.x;
    const float* he = g_f + cfg::OFF_H2E + (long)n * 1024;
    const float* hf = g_f + cfg::OFF_H2F + (long)n * 1024;
    float s = 0.f, s0 = 0.f, s1 = 0.f, s2 = 0.f;
    for (int j = t; j < 1024; j += 256) {
        s += he[j] * Weo[j];
        float hv = hf[j];
        s0 += hv * Wfo[j * 3 + 0];
        s1 += hv * Wfo[j * 3 + 1];
        s2 += hv * Wfo[j * 3 + 2];
    }
    __shared__ float sh[4][8];
#pragma unroll
    for (int o = 16; o > 0; o >>= 1) {
        s  += __shfl_down_sync(0xffffffffu, s,  o);
        s0 += __shfl_down_sync(0xffffffffu, s0, o);
        s1 += __shfl_down_sync(0xffffffffu, s1, o);
        s2 += __shfl_down_sync(0xffffffffu, s2, o);
    }
    if ((t & 31) == 0) {
        int w = t >> 5;
        sh[0][w] = s; sh[1][w] = s0; sh[2][w] = s1; sh[3][w] = s2;
    }
    __syncthreads();
    if (t == 0) {
        float t0 = 0.f, t1 = 0.f, t2 = 0.f, t3 = 0.f;
#pragma unroll
        for (int i = 0; i < 8; i++) { t0 += sh[0][i]; t1 += sh[1][i]; t2 += sh[2][i]; t3 += sh[3][i]; }
        out[n] = t0 + beo[0];
        out[(long)cfg::N + (long)n * 3 + 0] = t1 + bfo[0];
        out[(long)cfg::N + (long)n * 3 + 1] = t2 + bfo[1];
        out[(long)cfg::N + (long)n * 3 + 2] = t3 + bfo[2];
    }
}

// ===========================================================================
extern "C" void kernel_launch(void* const* d_in, const int* in_sizes, int n_in,
                              void* d_out, int out_size)
{
    const float* x        = (const float*)d_in[0];
    const int*   ei       = (const int*)  d_in[1];
    const float* att_bias = (const float*)d_in[2];
    const float* pos      = (const float*)d_in[3];
    const float* g_att  = (const float*)d_in[5];
    const float* b_att  = (const float*)d_in[6];
    const float* g_mlp  = (const float*)d_in[7];
    const float* b_mlp  = (const float*)d_in[8];
    const float* Wq     = (const float*)d_in[9];
    const float* bq     = (const float*)d_in[10];
    const float* Wk     = (const float*)d_in[11];
    const float* bk     = (const float*)d_in[12];
    const float* We_in  = (const float*)d_in[13];
    const float* be_in  = (const float*)d_in[14];
    const float* We_h   = (const float*)d_in[15];
    const float* be_h   = (const float*)d_in[16];
    const float* We_out = (const float*)d_in[17];
    const float* be_out = (const float*)d_in[18];
    const float* Wf_in  = (const float*)d_in[19];
    const float* bf_in  = (const float*)d_in[20];
    const float* Wf_h   = (const float*)d_in[21];
    const float* bf_h   = (const float*)d_in[22];
    const float* Wf_out = (const float*)d_in[23];
    const float* bf_out = (const float*)d_in[24];
    float* out = (float*)d_out;

    cudaFuncSetAttribute(tc_gemm<0>, cudaFuncAttributeMaxDynamicSharedMemorySize, GEMM_SMEM);
    cudaFuncSetAttribute(tc_gemm<2>, cudaFuncAttributeMaxDynamicSharedMemorySize, GEMM_SMEM);
    cudaFuncSetAttribute(tc_gemm<3>, cudaFuncAttributeMaxDynamicSharedMemorySize, GEMM_SMEM);
    cudaFuncSetAttribute(forces_h1_kernel, cudaFuncAttributeMaxDynamicSharedMemorySize, FIX_SMEM);

    const int MB = (cfg::N + 127) / 128;   // 157

    // 0: zero csr counts
    csr_zero<<<(cfg::N + 256) / 256, 256>>>();
    // 1: LayerNorm
    ln_kernel<<<cfg::N, 128>>>(x, g_att, b_att, g_mlp, b_mlp);
    // 2: biases
    bias_concat<<<20, 256>>>(bq, bk, be_in, bf_in, be_h, bf_h);
    // 3: weights
    conv_all<<<(unsigned)((3670016L + 255) / 256), 256>>>(Wq, Wk, We_in, Wf_in, We_h, Wf_h);
    // 4: csr count
    csr_count<<<(cfg::E + 255) / 256, 256>>>(ei);
    // 5: QK projection  (ncu -s 5 -c 1 captures this)
    tc_gemm<0><<<dim3(8, MB), 256, GEMM_SMEM>>>(cfg::B_ZATT_HI, cfg::B_ZATT_LO,
        cfg::B_WQK_HI, cfg::B_WQK_LO, cfg::OFF_BQK, 0, 0, cfg::OFF_QK, 0, 0,
        cfg::N, 1024, 512);
    // 6: csr scan
    csr_scan<<<1, 1024>>>();
    // 7: csr scatter
    csr_scatter<<<(cfg::E + 255) / 256, 256>>>(ei, att_bias);
    // 8: one-pass edge attention
    edge_attn_kernel<<<(cfg::N + 7) / 8, 256>>>(pos);
    // 9: fused in-projection [N,2048]
    tc_gemm<3><<<dim3(16, MB), 256, GEMM_SMEM>>>(cfg::B_ZMLP_HI, cfg::B_ZMLP_LO,
        cfg::B_WIN_HI, cfg::B_WIN_LO, cfg::OFF_BIN, 0, 0, cfg::OFF_RAWF,
        cfg::B_H1E_HI, cfg::B_H1E_LO, cfg::N, 2048, 512);
    // 10: forces h1 fixup
    forces_h1_kernel<<<cfg::N / 16, 256, FIX_SMEM>>>(Wf_in);
    // 11: energy hidden block
    tc_gemm<2><<<dim3(8, MB), 256, GEMM_SMEM>>>(cfg::B_H1E_HI, cfg::B_H1E_LO,
        cfg::B_WEH_HI, cfg::B_WEH_LO, cfg::OFF_BEH,
        cfg::B_H1E_HI, cfg::B_H1E_LO, cfg::OFF_H2E, 0, 0, cfg::N, 1024, 1024);
    // 12: forces hidden block
    tc_gemm<2><<<dim3(8, MB), 256, GEMM_SMEM>>>(cfg::B_H1F_HI, cfg::B_H1F_LO,
        cfg::B_WFH_HI, cfg::B_WFH_LO, cfg::OFF_BFH,
        cfg::B_H1F_HI, cfg::B_H1F_LO, cfg::OFF_H2F, 0, 0, cfg::N, 1024, 1024);
    // 13: output heads
    heads_kernel<<<cfg::N, 256>>>(We_out, be_out, Wf_out, bf_out, out);
}

// round 6
// speedup vs baseline: 1.3456x; 1.2246x over previous
#include <cuda_runtime.h>
#include <cuda_fp16.h>
#include <math.h>
#include <stdint.h>

#define DEV_INLINE __device__ __forceinline__

namespace cfg {
constexpr int N = 20000;
constexpr int E = 600000;
constexpr int D = 512;
constexpr int H = 8;
constexpr int HID = 1024;

// ---- fp32 scratch offsets ----
constexpr long OFF_QK   = 0;                          // N*1024 (q | k)
constexpr long OFF_CB   = OFF_QK  + (long)N * 1024;   // E (csr-permuted att_bias)
constexpr long OFF_ATT  = OFF_CB  + (long)E;          // N*24 (att/den - pos)
constexpr long OFF_RAWF = OFF_ATT + (long)N * 24;     // N*1024 (pre-gelu forces h1, partial)
constexpr long OFF_H2E  = OFF_RAWF+ (long)N * 1024;   // N*1024
constexpr long OFF_H2F  = OFF_H2E + (long)N * 1024;   // N*1024
constexpr long OFF_BQK  = OFF_H2F + (long)N * 1024;   // 1024
constexpr long OFF_BIN  = OFF_BQK + 1024;             // 2048
constexpr long OFF_BEH  = OFF_BIN + 2048;             // 1024
constexpr long OFF_BFH  = OFF_BEH + 1024;             // 1024
constexpr long FTOTAL   = OFF_BFH + 1024;

// ---- int scratch ----
constexpr long I_ROWPTR = 0;            // N+1
constexpr long I_WOFS   = N + 1;        // N+1
constexpr long I_COL    = 2 * (N + 1);  // E
constexpr long ITOTAL   = I_COL + E;

// ---- fp16 scratch offsets ----
constexpr long B_ZATT_HI = 0;
constexpr long B_ZATT_LO = B_ZATT_HI + (long)N * D;
constexpr long B_ZMLP_HI = B_ZATT_LO + (long)N * D;
constexpr long B_ZMLP_LO = B_ZMLP_HI + (long)N * D;
constexpr long B_H1E_HI  = B_ZMLP_LO + (long)N * D;
constexpr long B_H1E_LO  = B_H1E_HI  + (long)N * HID;
constexpr long B_H1F_HI  = B_H1E_LO  + (long)N * HID;
constexpr long B_H1F_LO  = B_H1F_HI  + (long)N * HID;
constexpr long B_WQK     = B_H1F_LO  + (long)N * HID;   // [1024, 512]  (hi only)
constexpr long B_WIN     = B_WQK     + 1024L * 512;     // [2048, 512]
constexpr long B_WEH     = B_WIN     + 2048L * 512;     // [1024, 1024]
constexpr long B_WFH     = B_WEH     + 1024L * 1024;
constexpr long BTOTAL    = B_WFH     + 1024L * 1024;
}

__device__ float  g_f[cfg::FTOTAL];
__device__ int    g_i[cfg::ITOTAL];
__device__ __half g_hf[cfg::BTOTAL];

// ===========================================================================
// helpers
// ===========================================================================
DEV_INLINE float gelu_tanh(float x) {
    float x3 = x * x * x;
    float t = tanhf(0.7978845608028654f * (x + 0.044715f * x3));
    return 0.5f * x * (1.0f + t);
}
DEV_INLINE void split_f16(float v, __half& h, __half& l) {
    h = __float2half(v);
    l = __float2half(v - __half2float(h));
}
DEV_INLINE uint32_t smem_u32(const void* p) {
    uint32_t a;
    asm("{ .reg .u64 t; cvta.to.shared.u64 t, %1; cvt.u32.u64 %0, t; }" : "=r"(a) : "l"(p));
    return a;
}
DEV_INLINE void cp16(uint32_t dst, const void* src, int szbytes) {
    asm volatile("cp.async.cg.shared.global [%0], [%1], 16, %2;\n" :: "r"(dst), "l"(src), "r"(szbytes));
}
DEV_INLINE void cp_commit() { asm volatile("cp.async.commit_group;\n"); }
template <int NN>
DEV_INLINE void cp_wait() { asm volatile("cp.async.wait_group %0;\n" :: "n"(NN) : "memory"); }

DEV_INLINE void ldsm_x4(uint32_t& r0, uint32_t& r1, uint32_t& r2, uint32_t& r3, uint32_t addr) {
    asm volatile("ldmatrix.sync.aligned.m8n8.x4.shared.b16 {%0,%1,%2,%3}, [%4];"
                 : "=r"(r0), "=r"(r1), "=r"(r2), "=r"(r3) : "r"(addr));
}
DEV_INLINE void mma16816(float* c, const uint32_t* a, const uint32_t* b) {
    asm volatile("mma.sync.aligned.m16n8k16.row.col.f32.f16.f16.f32 "
                 "{%0,%1,%2,%3}, {%4,%5,%6,%7}, {%8,%9}, {%0,%1,%2,%3};"
                 : "+f"(c[0]), "+f"(c[1]), "+f"(c[2]), "+f"(c[3])
                 : "r"(a[0]), "r"(a[1]), "r"(a[2]), "r"(a[3]), "r"(b[0]), "r"(b[1]));
}

// ===========================================================================
// split-fp16 HMMA GEMM: acc = (Ah+Al) @ Bh^T  (A exact 2-fp16 split, B fp16)
// MODE 0: C fp32 = acc + bias
// MODE 2: C fp32 = (resHi+resLo) + gelu(acc+bias)
// MODE 3: col<1024: gelu + split-fp16 -> oHi/oLo ; col>=1024: raw fp32 -> cOff
// CTA tile 128x128, BK=32, 8 warps (4m x 2n), 2-stage cp.async
// ===========================================================================
constexpr int PADK = 40;                      // 32 elems + 8 pad (80B row stride)
constexpr int MAT_BYTES = 128 * PADK * 2;     // 10240 per matrix
constexpr int STG_BYTES = 3 * MAT_BYTES;      // 30720 per stage (Ah, Al, Bh)
constexpr int GEMM_SMEM = 2 * STG_BYTES;      // 61440

template <int MODE>
__global__ __launch_bounds__(256) void tc_gemm(
    long aHi, long aLo, long bH, long biasOff,
    long resHi, long resLo, long cOff, long oHi, long oLo,
    int M, int Nc, int K)
{
    extern __shared__ char smem[];
    const uint32_t sb = smem_u32(smem);
    const int tid = threadIdx.x;
    const int wid = tid >> 5;
    const int lane = tid & 31;
    const int row0 = blockIdx.y * 128;
    const int col0 = blockIdx.x * 128;
    const int wm = wid & 3;
    const int wn = wid >> 2;

    const __half* Ah = g_hf + aHi;
    const __half* Al = g_hf + aLo;
    const __half* Bh = g_hf + bH;

    const int nChunks = K >> 5;

    auto load_stage = [&](int stage, int chunk) {
        const long k0 = (long)chunk << 5;
        const uint32_t base = sb + stage * STG_BYTES;
#pragma unroll
        for (int j = 0; j < 2; j++) {
            int i = tid + j * 256;         // 0..511
            int r = i >> 2;                // 0..127
            int seg = i & 3;               // 0..3
            uint32_t so = r * 80 + seg * 16;
            bool va = (row0 + r) < M;
            long ar = va ? (long)(row0 + r) : 0;
            cp16(base + so,                 Ah + ar * K + k0 + seg * 8, va ? 16 : 0);
            cp16(base + MAT_BYTES + so,     Al + ar * K + k0 + seg * 8, va ? 16 : 0);
            long br = (long)(col0 + r);
            cp16(base + 2 * MAT_BYTES + so, Bh + br * K + k0 + seg * 8, 16);
        }
    };

    float acc[2][8][4];
#pragma unroll
    for (int mt = 0; mt < 2; mt++)
#pragma unroll
        for (int nt = 0; nt < 8; nt++)
#pragma unroll
            for (int q = 0; q < 4; q++) acc[mt][nt][q] = 0.f;

    const int aRowOff = (lane & 7) + 8 * ((lane >> 3) & 1);
    const int aKbyte  = 16 * (lane >> 4);
    const int bRowOff = (lane & 7) + 8 * (lane >> 4);
    const int bKbyte  = 16 * ((lane >> 3) & 1);

    load_stage(0, 0);
    cp_commit();

    for (int c = 0; c < nChunks; c++) {
        if (c + 1 < nChunks) {
            load_stage((c + 1) & 1, c + 1);
            cp_commit();
            cp_wait<1>();
        } else {
            cp_wait<0>();
        }
        __syncthreads();

        const uint32_t st = sb + (c & 1) * STG_BYTES;
        const uint32_t baseAh = st;
        const uint32_t baseAl = st + MAT_BYTES;
        const uint32_t baseBh = st + 2 * MAT_BYTES;

#pragma unroll
        for (int kt = 0; kt < 2; kt++) {
            const int kb = kt * 32;
            uint32_t ah[2][4], al[2][4];
#pragma unroll
            for (int mt = 0; mt < 2; mt++) {
                uint32_t ro = (wm * 32 + mt * 16 + aRowOff) * 80 + kb + aKbyte;
                ldsm_x4(ah[mt][0], ah[mt][1], ah[mt][2], ah[mt][3], baseAh + ro);
                ldsm_x4(al[mt][0], al[mt][1], al[mt][2], al[mt][3], baseAl + ro);
            }
            uint32_t bh[8][2];
#pragma unroll
            for (int nt2 = 0; nt2 < 4; nt2++) {
                uint32_t ro = (wn * 64 + nt2 * 16 + bRowOff) * 80 + kb + bKbyte;
                ldsm_x4(bh[2 * nt2][0], bh[2 * nt2][1], bh[2 * nt2 + 1][0], bh[2 * nt2 + 1][1], baseBh + ro);
            }
#pragma unroll
            for (int mt = 0; mt < 2; mt++)
#pragma unroll
                for (int nt = 0; nt < 8; nt++) {
                    mma16816(acc[mt][nt], ah[mt], bh[nt]);
                    mma16816(acc[mt][nt], al[mt], bh[nt]);
                }
        }
        __syncthreads();
    }

    const int cRow = lane >> 2;
    const int cCol = 2 * (lane & 3);
#pragma unroll
    for (int mt = 0; mt < 2; mt++) {
#pragma unroll
        for (int half = 0; half < 2; half++) {
            int r = row0 + wm * 32 + mt * 16 + cRow + half * 8;
            if (r >= M) continue;
#pragma unroll
            for (int nt = 0; nt < 8; nt++) {
                int n = col0 + wn * 64 + nt * 8 + cCol;
                float v0 = acc[mt][nt][half * 2 + 0] + g_f[biasOff + n];
                float v1 = acc[mt][nt][half * 2 + 1] + g_f[biasOff + n + 1];
                if (MODE == 0) {
                    long gidx = (long)r * Nc + n;
                    *reinterpret_cast<float2*>(g_f + cOff + gidx) = make_float2(v0, v1);
                } else if (MODE == 2) {
                    v0 = gelu_tanh(v0); v1 = gelu_tanh(v1);
                    long gidx = (long)r * Nc + n;
                    __half2 rh = *reinterpret_cast<const __half2*>(g_hf + resHi + gidx);
                    __half2 rl = *reinterpret_cast<const __half2*>(g_hf + resLo + gidx);
                    v0 += __half2float(rh.x) + __half2float(rl.x);
                    v1 += __half2float(rh.y) + __half2float(rl.y);
                    *reinterpret_cast<float2*>(g_f + cOff + gidx) = make_float2(v0, v1);
                } else {  // MODE 3
                    if (n < 1024) {
                        float gv0 = gelu_tanh(v0), gv1 = gelu_tanh(v1);
                        long gidx = (long)r * 1024 + n;
                        __half h0, l0, h1, l1;
                        split_f16(gv0, h0, l0);
                        split_f16(gv1, h1, l1);
                        __half2 hh; hh.x = h0; hh.y = h1;
                        __half2 ll; ll.x = l0; ll.y = l1;
                        *reinterpret_cast<__half2*>(g_hf + oHi + gidx) = hh;
                        *reinterpret_cast<__half2*>(g_hf + oLo + gidx) = ll;
                    } else {
                        long gidx = (long)r * 1024 + (n - 1024);
                        *reinterpret_cast<float2*>(g_f + cOff + gidx) = make_float2(v0, v1);
                    }
                }
            }
        }
    }
}

// ===========================================================================
// weight conversion (transpose, fp16 hi only)
// ===========================================================================
__global__ void conv_all(const float* __restrict__ Wq, const float* __restrict__ Wk,
                         const float* __restrict__ Wei, const float* __restrict__ Wfi,
                         const float* __restrict__ Weh, const float* __restrict__ Wfh)
{
    long i = (long)blockIdx.x * blockDim.x + threadIdx.x;
    if (i >= 3670016L) return;
    const float* W; long o, dst; int NcS, Kd;
    if (i < 262144L)       { W = Wq;  o = i;            dst = cfg::B_WQK;          NcS = 512;  Kd = 512; }
    else if (i < 524288L)  { W = Wk;  o = i - 262144L;  dst = cfg::B_WQK + 262144; NcS = 512;  Kd = 512; }
    else if (i < 1048576L) { W = Wei; o = i - 524288L;  dst = cfg::B_WIN;          NcS = 1024; Kd = 512; }
    else if (i < 1572864L) { W = Wfi; o = i - 1048576L; dst = cfg::B_WIN + 524288; NcS = 1024; Kd = 512; }
    else if (i < 2621440L) { W = Weh; o = i - 1572864L; dst = cfg::B_WEH;          NcS = 1024; Kd = 1024; }
    else                   { W = Wfh; o = i - 2621440L; dst = cfg::B_WFH;          NcS = 1024; Kd = 1024; }
    int n = (int)(o / Kd);
    int k = (int)(o % Kd);
    g_hf[dst + o] = __float2half(W[(long)k * NcS + n]);
}

__global__ void bias_concat(const float* __restrict__ bq, const float* __restrict__ bk,
                            const float* __restrict__ bei, const float* __restrict__ bfi,
                            const float* __restrict__ beh, const float* __restrict__ bfh)
{
    int i = blockIdx.x * blockDim.x + threadIdx.x;
    if (i < 1024) g_f[cfg::OFF_BQK + i] = (i < 512) ? bq[i] : bk[i - 512];
    else if (i < 3072) { int j = i - 1024; g_f[cfg::OFF_BIN + j] = (j < 1024) ? bei[j] : bfi[j - 1024]; }
    else if (i < 4096) g_f[cfg::OFF_BEH + i - 3072] = beh[i - 3072];
    else if (i < 5120) g_f[cfg::OFF_BFH + i - 4096] = bfh[i - 4096];
}

// ===========================================================================
// CSR build
// ===========================================================================
__global__ void csr_zero() {
    int i = blockIdx.x * blockDim.x + threadIdx.x;
    if (i <= cfg::N) g_i[cfg::I_WOFS + i] = 0;
}
__global__ void csr_count(const int* __restrict__ ei) {
    int e = blockIdx.x * blockDim.x + threadIdx.x;
    if (e < cfg::E) atomicAdd(&g_i[cfg::I_WOFS + ei[e]], 1);
}
__global__ __launch_bounds__(1024) void csr_scan() {
    __shared__ int sh[1024];
    int t = threadIdx.x;
    int loc[20];
    int base = t * 20;
    int sum = 0;
#pragma unroll
    for (int j = 0; j < 20; j++) {
        int idx = base + j;
        int v = (idx < cfg::N) ? g_i[cfg::I_WOFS + idx] : 0;
        loc[j] = sum;
        sum += v;
    }
    sh[t] = sum;
    __syncthreads();
    for (int off = 1; off < 1024; off <<= 1) {
        int v = (t >= off) ? sh[t - off] : 0;
        __syncthreads();
        sh[t] += v;
        __syncthreads();
    }
    int pre = (t == 0) ? 0 : sh[t - 1];
#pragma unroll
    for (int j = 0; j < 20; j++) {
        int idx = base + j;
        if (idx < cfg::N) {
            g_i[cfg::I_ROWPTR + idx] = pre + loc[j];
            g_i[cfg::I_WOFS + idx]   = pre + loc[j];
        }
    }
    if (t == 0) g_i[cfg::I_ROWPTR + cfg::N] = cfg::E;
}
__global__ void csr_scatter(const int* __restrict__ ei, const float* __restrict__ att_bias) {
    int e = blockIdx.x * blockDim.x + threadIdx.x;
    if (e >= cfg::E) return;
    int r = ei[e];
    int p = atomicAdd(&g_i[cfg::I_WOFS + r], 1);
    g_i[cfg::I_COL + p] = ei[cfg::E + e];
    g_f[cfg::OFF_CB + p] = att_bias[e];
}

// ===========================================================================
// one-pass edge attention: warp per node, online softmax + position average
// ===========================================================================
__global__ __launch_bounds__(256) void edge_attn_kernel(const float* __restrict__ pos) {
    int n = blockIdx.x * 8 + (threadIdx.x >> 5);
    if (n >= cfg::N) return;
    int lane = threadIdx.x & 31;

    int base = g_i[cfg::I_ROWPTR + n];
    int deg  = g_i[cfg::I_ROWPTR + n + 1] - base;

    const float4* qr = reinterpret_cast<const float4*>(g_f + cfg::OFF_QK + (long)n * 1024) + lane * 4;
    float4 q0 = qr[0], q1 = qr[1], q2 = qr[2], q3 = qr[3];

    float prv = (lane < 3) ? pos[(long)n * 3 + lane] : 0.f;
    float prx = __shfl_sync(0xffffffffu, prv, 0);
    float pry = __shfl_sync(0xffffffffu, prv, 1);
    float prz = __shfl_sync(0xffffffffu, prv, 2);

    float m = -1e30f, d = 0.f, a0 = 0.f, a1 = 0.f, a2 = 0.f;

    for (int i = 0; i < deg; i++) {
        int c = g_i[cfg::I_COL + base + i];
        float bias = g_f[cfg::OFF_CB + base + i];
        const float4* kr = reinterpret_cast<const float4*>(g_f + cfg::OFF_QK + (long)c * 1024 + 512) + lane * 4;
        float4 k0 = kr[0], k1 = kr[1], k2 = kr[2], k3 = kr[3];
        float s = q0.x*k0.x + q0.y*k0.y + q0.z*k0.z + q0.w*k0.w
                + q1.x*k1.x + q1.y*k1.y + q1.z*k1.z + q1.w*k1.w
                + q2.x*k2.x + q2.y*k2.y + q2.z*k2.z + q2.w*k2.w
                + q3.x*k3.x + q3.y*k3.y + q3.z*k3.z + q3.w*k3.w;
        s += __shfl_xor_sync(0xffffffffu, s, 1);
        s += __shfl_xor_sync(0xffffffffu, s, 2);

        float pv = (lane < 3) ? pos[(long)c * 3 + lane] : 0.f;
        float px = __shfl_sync(0xffffffffu, pv, 0);
        float py = __shfl_sync(0xffffffffu, pv, 1);
        float pz = __shfl_sync(0xffffffffu, pv, 2);

        float lg = s * 0.125f + bias;
        float nm = fmaxf(m, lg);
        float sc = expf(m - nm);
        float p  = expf(lg - nm);
        d  = d  * sc + p;
        a0 = a0 * sc + p * px;
        a1 = a1 * sc + p * py;
        a2 = a2 * sc + p * pz;
        m = nm;
    }

    if ((lane & 3) == 0) {
        int h = lane >> 2;
        float inv = (d > 0.f) ? 1.0f / d : 0.f;
        long o = (long)n * 24 + h * 3;
        g_f[cfg::OFF_ATT + o + 0] = a0 * inv - prx;
        g_f[cfg::OFF_ATT + o + 1] = a1 * inv - pry;
        g_f[cfg::OFF_ATT + o + 2] = a2 * inv - prz;
    }
}

// ===========================================================================
// forces h1 fixup: h1f = gelu(raw + attminus @ W24) -> split fp16
// ===========================================================================
constexpr int FIX_SMEM = (24 * 1025 + 16 * 24) * 4;

__global__ __launch_bounds__(256) void forces_h1_kernel(const float* __restrict__ Wfi) {
    extern __shared__ float sw[];
    float* w24 = sw;
    float* am  = sw + 24 * 1025;
    int n0 = blockIdx.x * 16;
    int t = threadIdx.x;

    for (int idx = t; idx < 24 * 1024; idx += 256) {
        int k = idx >> 10, j = idx & 1023;
        w24[k * 1025 + j] = Wfi[(long)(512 + k) * 1024 + j];
    }
    for (int idx = t; idx < 16 * 24; idx += 256) {
        int i = idx / 24, k = idx % 24;
        am[idx] = g_f[cfg::OFF_ATT + (long)(n0 + i) * 24 + k];
    }
    __syncthreads();

#pragma unroll
    for (int jj = 0; jj < 4; jj++) {
        int j = t + jj * 256;
        float w[24];
#pragma unroll
        for (int k = 0; k < 24; k++) w[k] = w24[k * 1025 + j];
        for (int i = 0; i < 16; i++) {
            long gi = (long)(n0 + i) * 1024 + j;
            float v = g_f[cfg::OFF_RAWF + gi];
#pragma unroll
            for (int k = 0; k < 24; k++) v = fmaf(am[i * 24 + k], w[k], v);
            v = gelu_tanh(v);
            __half hh, ll;
            split_f16(v, hh, ll);
            g_hf[cfg::B_H1F_HI + gi] = hh;
            g_hf[cfg::B_H1F_LO + gi] = ll;
        }
    }
}

// ===========================================================================
// double LayerNorm -> split fp16 activations
// ===========================================================================
__global__ __launch_bounds__(128) void ln_kernel(
    const float* __restrict__ x,
    const float* __restrict__ ga, const float* __restrict__ ba,
    const float* __restrict__ gm, const float* __restrict__ bm)
{
    int row = blockIdx.x;
    int t = threadIdx.x;
    const float* xr = x + (long)row * cfg::D;

    float v[4];
    float s = 0.f, ss = 0.f;
#pragma unroll
    for (int i = 0; i < 4; i++) {
        v[i] = xr[t + 128 * i];
        s += v[i];
        ss += v[i] * v[i];
    }
    __shared__ float sh[2][4];
#pragma unroll
    for (int o = 16; o > 0; o >>= 1) {
        s  += __shfl_down_sync(0xffffffffu, s, o);
        ss += __shfl_down_sync(0xffffffffu, ss, o);
    }
    if ((t & 31) == 0) { sh[0][t >> 5] = s; sh[1][t >> 5] = ss; }
    __syncthreads();
    if (t == 0) {
        float S  = sh[0][0] + sh[0][1] + sh[0][2] + sh[0][3];
        float SS = sh[1][0] + sh[1][1] + sh[1][2] + sh[1][3];
        float mean = S / cfg::D;
        float var  = SS / cfg::D - mean * mean;
        sh[0][0] = mean;
        sh[1][0] = rsqrtf(var + 1e-5f);
    }
    __syncthreads();
    float mean = sh[0][0], rstd = sh[1][0];
#pragma unroll
    for (int i = 0; i < 4; i++) {
        int c = t + 128 * i;
        float zn = (v[i] - mean) * rstd;
        float za = zn * ga[c] + ba[c];
        float zm = zn * gm[c] + bm[c];
        __half h, l;
        split_f16(za, h, l);
        g_hf[cfg::B_ZATT_HI + (long)row * cfg::D + c] = h;
        g_hf[cfg::B_ZATT_LO + (long)row * cfg::D + c] = l;
        split_f16(zm, h, l);
        g_hf[cfg::B_ZMLP_HI + (long)row * cfg::D + c] = h;
        g_hf[cfg::B_ZMLP_LO + (long)row * cfg::D + c] = l;
    }
}

// ===========================================================================
// fused output heads
// ===========================================================================
__global__ __launch_bounds__(256) void heads_kernel(
    const float* __restrict__ Weo, const float* __restrict__ beo,
    const float* __restrict__ Wfo, const float* __restrict__ bfo,
    float* __restrict__ out)
{
    int n = blockIdx.x;
    int t = threadIdx.x;
    const float* he = g_f + cfg::OFF_H2E + (long)n * 1024;
    const float* hf = g_f + cfg::OFF_H2F + (long)n * 1024;
    float s = 0.f, s0 = 0.f, s1 = 0.f, s2 = 0.f;
    for (int j = t; j < 1024; j += 256) {
        s += he[j] * Weo[j];
        float hv = hf[j];
        s0 += hv * Wfo[j * 3 + 0];
        s1 += hv * Wfo[j * 3 + 1];
        s2 += hv * Wfo[j * 3 + 2];
    }
    __shared__ float sh[4][8];
#pragma unroll
    for (int o = 16; o > 0; o >>= 1) {
        s  += __shfl_down_sync(0xffffffffu, s,  o);
        s0 += __shfl_down_sync(0xffffffffu, s0, o);
        s1 += __shfl_down_sync(0xffffffffu, s1, o);
        s2 += __shfl_down_sync(0xffffffffu, s2, o);
    }
    if ((t & 31) == 0) {
        int w = t >> 5;
        sh[0][w] = s; sh[1][w] = s0; sh[2][w] = s1; sh[3][w] = s2;
    }
    __syncthreads();
    if (t == 0) {
        float t0 = 0.f, t1 = 0.f, t2 = 0.f, t3 = 0.f;
#pragma unroll
        for (int i = 0; i < 8; i++) { t0 += sh[0][i]; t1 += sh[1][i]; t2 += sh[2][i]; t3 += sh[3][i]; }
        out[n] = t0 + beo[0];
        out[(long)cfg::N + (long)n * 3 + 0] = t1 + bfo[0];
        out[(long)cfg::N + (long)n * 3 + 1] = t2 + bfo[1];
        out[(long)cfg::N + (long)n * 3 + 2] = t3 + bfo[2];
    }
}

// ===========================================================================
extern "C" void kernel_launch(void* const* d_in, const int* in_sizes, int n_in,
                              void* d_out, int out_size)
{
    const float* x        = (const float*)d_in[0];
    const int*   ei       = (const int*)  d_in[1];
    const float* att_bias = (const float*)d_in[2];
    const float* pos      = (const float*)d_in[3];
    const float* g_att  = (const float*)d_in[5];
    const float* b_att  = (const float*)d_in[6];
    const float* g_mlp  = (const float*)d_in[7];
    const float* b_mlp  = (const float*)d_in[8];
    const float* Wq     = (const float*)d_in[9];
    const float* bq     = (const float*)d_in[10];
    const float* Wk     = (const float*)d_in[11];
    const float* bk     = (const float*)d_in[12];
    const float* We_in  = (const float*)d_in[13];
    const float* be_in  = (const float*)d_in[14];
    const float* We_h   = (const float*)d_in[15];
    const float* be_h   = (const float*)d_in[16];
    const float* We_out = (const float*)d_in[17];
    const float* be_out = (const float*)d_in[18];
    const float* Wf_in  = (const float*)d_in[19];
    const float* bf_in  = (const float*)d_in[20];
    const float* Wf_h   = (const float*)d_in[21];
    const float* bf_h   = (const float*)d_in[22];
    const float* Wf_out = (const float*)d_in[23];
    const float* bf_out = (const float*)d_in[24];
    float* out = (float*)d_out;

    cudaFuncSetAttribute(tc_gemm<0>, cudaFuncAttributeMaxDynamicSharedMemorySize, GEMM_SMEM);
    cudaFuncSetAttribute(tc_gemm<2>, cudaFuncAttributeMaxDynamicSharedMemorySize, GEMM_SMEM);
    cudaFuncSetAttribute(tc_gemm<3>, cudaFuncAttributeMaxDynamicSharedMemorySize, GEMM_SMEM);
    cudaFuncSetAttribute(forces_h1_kernel, cudaFuncAttributeMaxDynamicSharedMemorySize, FIX_SMEM);

    const int MB = (cfg::N + 127) / 128;   // 157

    // 0: zero csr counts
    csr_zero<<<(cfg::N + 256) / 256, 256>>>();
    // 1: LayerNorm
    ln_kernel<<<cfg::N, 128>>>(x, g_att, b_att, g_mlp, b_mlp);
    // 2: biases
    bias_concat<<<20, 256>>>(bq, bk, be_in, bf_in, be_h, bf_h);
    // 3: weights
    conv_all<<<(unsigned)((3670016L + 255) / 256), 256>>>(Wq, Wk, We_in, Wf_in, We_h, Wf_h);
    // 4: csr count
    csr_count<<<(cfg::E + 255) / 256, 256>>>(ei);
    // 5: QK projection
    tc_gemm<0><<<dim3(8, MB), 256, GEMM_SMEM>>>(cfg::B_ZATT_HI, cfg::B_ZATT_LO,
        cfg::B_WQK, cfg::OFF_BQK, 0, 0, cfg::OFF_QK, 0, 0, cfg::N, 1024, 512);
    // 6: csr scan
    csr_scan<<<1, 1024>>>();
    // 7: csr scatter
    csr_scatter<<<(cfg::E + 255) / 256, 256>>>(ei, att_bias);
    // 8: one-pass edge attention
    edge_attn_kernel<<<(cfg::N + 7) / 8, 256>>>(pos);
    // 9: fused in-projection [N,2048]
    tc_gemm<3><<<dim3(16, MB), 256, GEMM_SMEM>>>(cfg::B_ZMLP_HI, cfg::B_ZMLP_LO,
        cfg::B_WIN, cfg::OFF_BIN, 0, 0, cfg::OFF_RAWF,
        cfg::B_H1E_HI, cfg::B_H1E_LO, cfg::N, 2048, 512);
    // 10: forces h1 fixup
    forces_h1_kernel<<<cfg::N / 16, 256, FIX_SMEM>>>(Wf_in);
    // 11: energy hidden block
    tc_gemm<2><<<dim3(8, MB), 256, GEMM_SMEM>>>(cfg::B_H1E_HI, cfg::B_H1E_LO,
        cfg::B_WEH, cfg::OFF_BEH,
        cfg::B_H1E_HI, cfg::B_H1E_LO, cfg::OFF_H2E, 0, 0, cfg::N, 1024, 1024);
    // 12: forces hidden block
    tc_gemm<2><<<dim3(8, MB), 256, GEMM_SMEM>>>(cfg::B_H1F_HI, cfg::B_H1F_LO,
        cfg::B_WFH, cfg::OFF_BFH,
        cfg::B_H1F_HI, cfg::B_H1F_LO, cfg::OFF_H2F, 0, 0, cfg::N, 1024, 1024);
    // 13: output heads
    heads_kernel<<<cfg::N, 256>>>(We_out, be_out, Wf_out, bf_out, out);
}

// round 7
// speedup vs baseline: 1.7396x; 1.2928x over previous
#include <cuda_runtime.h>
#include <cuda_fp16.h>
#include <math.h>
#include <stdint.h>

#define DEV_INLINE __device__ __forceinline__

namespace cfg {
constexpr int N = 20000;
constexpr int E = 600000;
constexpr int D = 512;
constexpr int H = 8;
constexpr int HID = 1024;

// ---- fp32 scratch offsets ----
constexpr long OFF_QK   = 0;                          // N*1024 (q | k)
constexpr long OFF_CB   = OFF_QK  + (long)N * 1024;   // E (csr-permuted att_bias)
constexpr long OFF_ATT  = OFF_CB  + (long)E;          // N*24 (att/den - pos)
constexpr long OFF_RAWF = OFF_ATT + (long)N * 24;     // N*1024 (pre-gelu forces h1, partial)
constexpr long OFF_H2E  = OFF_RAWF+ (long)N * 1024;   // N*1024
constexpr long OFF_H2F  = OFF_H2E + (long)N * 1024;   // N*1024
constexpr long OFF_BQK  = OFF_H2F + (long)N * 1024;   // 1024
constexpr long OFF_BIN  = OFF_BQK + 1024;             // 2048
constexpr long OFF_BEH  = OFF_BIN + 2048;             // 1024
constexpr long OFF_BFH  = OFF_BEH + 1024;             // 1024
constexpr long FTOTAL   = OFF_BFH + 1024;

// ---- int scratch ----
constexpr long I_ROWPTR = 0;            // N+1
constexpr long I_WOFS   = N + 1;        // N+1
constexpr long I_COL    = 2 * (N + 1);  // E
constexpr long ITOTAL   = I_COL + E;

// ---- fp16 scratch offsets ----
constexpr long B_ZATT = 0;
constexpr long B_ZMLP = B_ZATT + (long)N * D;
constexpr long B_H1E  = B_ZMLP + (long)N * D;
constexpr long B_H1F  = B_H1E  + (long)N * HID;
constexpr long B_WQK  = B_H1F  + (long)N * HID;   // [1024, 512]
constexpr long B_WIN  = B_WQK  + 1024L * 512;     // [2048, 512]
constexpr long B_WEH  = B_WIN  + 2048L * 512;     // [1024, 1024]
constexpr long B_WFH  = B_WEH  + 1024L * 1024;
constexpr long BTOTAL = B_WFH  + 1024L * 1024;
}

__device__ float  g_f[cfg::FTOTAL];
__device__ int    g_i[cfg::ITOTAL];
__device__ __half g_hf[cfg::BTOTAL];

// ===========================================================================
// helpers
// ===========================================================================
DEV_INLINE float gelu_tanh(float x) {
    float x3 = x * x * x;
    float t = tanhf(0.7978845608028654f * (x + 0.044715f * x3));
    return 0.5f * x * (1.0f + t);
}
DEV_INLINE uint32_t smem_u32(const void* p) {
    uint32_t a;
    asm("{ .reg .u64 t; cvta.to.shared.u64 t, %1; cvt.u32.u64 %0, t; }" : "=r"(a) : "l"(p));
    return a;
}
DEV_INLINE void cp16(uint32_t dst, const void* src, int szbytes) {
    asm volatile("cp.async.cg.shared.global [%0], [%1], 16, %2;\n" :: "r"(dst), "l"(src), "r"(szbytes));
}
DEV_INLINE void cp_commit() { asm volatile("cp.async.commit_group;\n"); }
template <int NN>
DEV_INLINE void cp_wait() { asm volatile("cp.async.wait_group %0;\n" :: "n"(NN) : "memory"); }

DEV_INLINE void ldsm_x4(uint32_t& r0, uint32_t& r1, uint32_t& r2, uint32_t& r3, uint32_t addr) {
    asm volatile("ldmatrix.sync.aligned.m8n8.x4.shared.b16 {%0,%1,%2,%3}, [%4];"
                 : "=r"(r0), "=r"(r1), "=r"(r2), "=r"(r3) : "r"(addr));
}
DEV_INLINE void mma16816(float* c, const uint32_t* a, const uint32_t* b) {
    asm volatile("mma.sync.aligned.m16n8k16.row.col.f32.f16.f16.f32 "
                 "{%0,%1,%2,%3}, {%4,%5,%6,%7}, {%8,%9}, {%0,%1,%2,%3};"
                 : "+f"(c[0]), "+f"(c[1]), "+f"(c[2]), "+f"(c[3])
                 : "r"(a[0]), "r"(a[1]), "r"(a[2]), "r"(a[3]), "r"(b[0]), "r"(b[1]));
}

// ===========================================================================
// fp16 HMMA GEMM (fp32 accumulate): acc = A @ B^T
// MODE 0: C fp32 = acc + bias
// MODE 2: C fp32 = res(fp16) + gelu(acc+bias)
// MODE 3: col<1024: gelu -> fp16 oH ; col>=1024: raw fp32 -> cOff
// CTA tile 128x128, BK=32, 8 warps (4m x 2n), 3-stage cp.async pipeline
// ===========================================================================
constexpr int PADK = 40;                      // 32 elems + 8 pad (80B row stride)
constexpr int MAT_BYTES = 128 * PADK * 2;     // 10240 per matrix
constexpr int STG_BYTES = 2 * MAT_BYTES;      // 20480 per stage (A, B)
constexpr int GEMM_SMEM = 3 * STG_BYTES;      // 61440

template <int MODE>
__global__ __launch_bounds__(256) void tc_gemm(
    long aOff, long bOff, long biasOff,
    long resOff, long cOff, long oH,
    int M, int Nc, int K)
{
    extern __shared__ char smem[];
    const uint32_t sb = smem_u32(smem);
    const int tid = threadIdx.x;
    const int wid = tid >> 5;
    const int lane = tid & 31;
    const int row0 = blockIdx.y * 128;
    const int col0 = blockIdx.x * 128;
    const int wm = wid & 3;
    const int wn = wid >> 2;

    const __half* A = g_hf + aOff;
    const __half* B = g_hf + bOff;

    const int nChunks = K >> 5;

    auto load_stage = [&](int stage, int chunk) {
        const long k0 = (long)chunk << 5;
        const uint32_t base = sb + stage * STG_BYTES;
#pragma unroll
        for (int j = 0; j < 2; j++) {
            int i = tid + j * 256;         // 0..511
            int r = i >> 2;                // 0..127
            int seg = i & 3;               // 0..3
            uint32_t so = r * 80 + seg * 16;
            bool va = (row0 + r) < M;
            long ar = va ? (long)(row0 + r) : 0;
            cp16(base + so,             A + ar * K + k0 + seg * 8, va ? 16 : 0);
            long br = (long)(col0 + r);
            cp16(base + MAT_BYTES + so, B + br * K + k0 + seg * 8, 16);
        }
    };

    float acc[2][8][4];
#pragma unroll
    for (int mt = 0; mt < 2; mt++)
#pragma unroll
        for (int nt = 0; nt < 8; nt++)
#pragma unroll
            for (int q = 0; q < 4; q++) acc[mt][nt][q] = 0.f;

    const int aRowOff = (lane & 7) + 8 * ((lane >> 3) & 1);
    const int aKbyte  = 16 * (lane >> 4);
    const int bRowOff = (lane & 7) + 8 * (lane >> 4);
    const int bKbyte  = 16 * ((lane >> 3) & 1);

    load_stage(0, 0);
    cp_commit();
    if (nChunks > 1) { load_stage(1, 1); cp_commit(); }

    for (int c = 0; c < nChunks; c++) {
        if (c + 1 < nChunks) cp_wait<1>(); else cp_wait<0>();
        __syncthreads();

        const uint32_t st = sb + (c % 3) * STG_BYTES;
        const uint32_t baseA = st;
        const uint32_t baseB = st + MAT_BYTES;

#pragma unroll
        for (int kt = 0; kt < 2; kt++) {
            const int kb = kt * 32;
            uint32_t a[2][4];
#pragma unroll
            for (int mt = 0; mt < 2; mt++) {
                uint32_t ro = (wm * 32 + mt * 16 + aRowOff) * 80 + kb + aKbyte;
                ldsm_x4(a[mt][0], a[mt][1], a[mt][2], a[mt][3], baseA + ro);
            }
            uint32_t b[8][2];
#pragma unroll
            for (int nt2 = 0; nt2 < 4; nt2++) {
                uint32_t ro = (wn * 64 + nt2 * 16 + bRowOff) * 80 + kb + bKbyte;
                ldsm_x4(b[2 * nt2][0], b[2 * nt2][1], b[2 * nt2 + 1][0], b[2 * nt2 + 1][1], baseB + ro);
            }
#pragma unroll
            for (int mt = 0; mt < 2; mt++)
#pragma unroll
                for (int nt = 0; nt < 8; nt++)
                    mma16816(acc[mt][nt], a[mt], b[nt]);
        }
        __syncthreads();
        if (c + 2 < nChunks) {
            load_stage((c + 2) % 3, c + 2);
            cp_commit();
        }
    }

    const int cRow = lane >> 2;
    const int cCol = 2 * (lane & 3);
#pragma unroll
    for (int mt = 0; mt < 2; mt++) {
#pragma unroll
        for (int half = 0; half < 2; half++) {
            int r = row0 + wm * 32 + mt * 16 + cRow + half * 8;
            if (r >= M) continue;
#pragma unroll
            for (int nt = 0; nt < 8; nt++) {
                int n = col0 + wn * 64 + nt * 8 + cCol;
                float v0 = acc[mt][nt][half * 2 + 0] + g_f[biasOff + n];
                float v1 = acc[mt][nt][half * 2 + 1] + g_f[biasOff + n + 1];
                if (MODE == 0) {
                    long gidx = (long)r * Nc + n;
                    *reinterpret_cast<float2*>(g_f + cOff + gidx) = make_float2(v0, v1);
                } else if (MODE == 2) {
                    v0 = gelu_tanh(v0); v1 = gelu_tanh(v1);
                    long gidx = (long)r * Nc + n;
                    __half2 rh = *reinterpret_cast<const __half2*>(g_hf + resOff + gidx);
                    v0 += __half2float(rh.x);
                    v1 += __half2float(rh.y);
                    *reinterpret_cast<float2*>(g_f + cOff + gidx) = make_float2(v0, v1);
                } else {  // MODE 3
                    if (n < 1024) {
                        float gv0 = gelu_tanh(v0), gv1 = gelu_tanh(v1);
                        long gidx = (long)r * 1024 + n;
                        __half2 hh; hh.x = __float2half(gv0); hh.y = __float2half(gv1);
                        *reinterpret_cast<__half2*>(g_hf + oH + gidx) = hh;
                    } else {
                        long gidx = (long)r * 1024 + (n - 1024);
                        *reinterpret_cast<float2*>(g_f + cOff + gidx) = make_float2(v0, v1);
                    }
                }
            }
        }
    }
}

// ===========================================================================
// weight conversion (transpose, fp16)
// ===========================================================================
__global__ void conv_all(const float* __restrict__ Wq, const float* __restrict__ Wk,
                         const float* __restrict__ Wei, const float* __restrict__ Wfi,
                         const float* __restrict__ Weh, const float* __restrict__ Wfh)
{
    long i = (long)blockIdx.x * blockDim.x + threadIdx.x;
    if (i >= 3670016L) return;
    const float* W; long o, dst; int NcS, Kd;
    if (i < 262144L)       { W = Wq;  o = i;            dst = cfg::B_WQK;          NcS = 512;  Kd = 512; }
    else if (i < 524288L)  { W = Wk;  o = i - 262144L;  dst = cfg::B_WQK + 262144; NcS = 512;  Kd = 512; }
    else if (i < 1048576L) { W = Wei; o = i - 524288L;  dst = cfg::B_WIN;          NcS = 1024; Kd = 512; }
    else if (i < 1572864L) { W = Wfi; o = i - 1048576L; dst = cfg::B_WIN + 524288; NcS = 1024; Kd = 512; }
    else if (i < 2621440L) { W = Weh; o = i - 1572864L; dst = cfg::B_WEH;          NcS = 1024; Kd = 1024; }
    else                   { W = Wfh; o = i - 2621440L; dst = cfg::B_WFH;          NcS = 1024; Kd = 1024; }
    int n = (int)(o / Kd);
    int k = (int)(o % Kd);
    g_hf[dst + o] = __float2half(W[(long)k * NcS + n]);
}

__global__ void bias_concat(const float* __restrict__ bq, const float* __restrict__ bk,
                            const float* __restrict__ bei, const float* __restrict__ bfi,
                            const float* __restrict__ beh, const float* __restrict__ bfh)
{
    int i = blockIdx.x * blockDim.x + threadIdx.x;
    if (i < 1024) g_f[cfg::OFF_BQK + i] = (i < 512) ? bq[i] : bk[i - 512];
    else if (i < 3072) { int j = i - 1024; g_f[cfg::OFF_BIN + j] = (j < 1024) ? bei[j] : bfi[j - 1024]; }
    else if (i < 4096) g_f[cfg::OFF_BEH + i - 3072] = beh[i - 3072];
    else if (i < 5120) g_f[cfg::OFF_BFH + i - 4096] = bfh[i - 4096];
}

// ===========================================================================
// CSR build
// ===========================================================================
__global__ void csr_zero() {
    int i = blockIdx.x * blockDim.x + threadIdx.x;
    if (i <= cfg::N) g_i[cfg::I_WOFS + i] = 0;
}
__global__ void csr_count(const int* __restrict__ ei) {
    int e = blockIdx.x * blockDim.x + threadIdx.x;
    if (e < cfg::E) atomicAdd(&g_i[cfg::I_WOFS + ei[e]], 1);
}
__global__ __launch_bounds__(1024) void csr_scan() {
    __shared__ int sh[1024];
    int t = threadIdx.x;
    int loc[20];
    int base = t * 20;
    int sum = 0;
#pragma unroll
    for (int j = 0; j < 20; j++) {
        int idx = base + j;
        int v = (idx < cfg::N) ? g_i[cfg::I_WOFS + idx] : 0;
        loc[j] = sum;
        sum += v;
    }
    sh[t] = sum;
    __syncthreads();
    for (int off = 1; off < 1024; off <<= 1) {
        int v = (t >= off) ? sh[t - off] : 0;
        __syncthreads();
        sh[t] += v;
        __syncthreads();
    }
    int pre = (t == 0) ? 0 : sh[t - 1];
#pragma unroll
    for (int j = 0; j < 20; j++) {
        int idx = base + j;
        if (idx < cfg::N) {
            g_i[cfg::I_ROWPTR + idx] = pre + loc[j];
            g_i[cfg::I_WOFS + idx]   = pre + loc[j];
        }
    }
    if (t == 0) g_i[cfg::I_ROWPTR + cfg::N] = cfg::E;
}
__global__ void csr_scatter(const int* __restrict__ ei, const float* __restrict__ att_bias) {
    int e = blockIdx.x * blockDim.x + threadIdx.x;
    if (e >= cfg::E) return;
    int r = ei[e];
    int p = atomicAdd(&g_i[cfg::I_WOFS + r], 1);
    g_i[cfg::I_COL + p] = ei[cfg::E + e];
    g_f[cfg::OFF_CB + p] = att_bias[e];
}

// ===========================================================================
// one-pass edge attention: warp per node, online softmax + position average
// ===========================================================================
__global__ __launch_bounds__(256) void edge_attn_kernel(const float* __restrict__ pos) {
    int n = blockIdx.x * 8 + (threadIdx.x >> 5);
    if (n >= cfg::N) return;
    int lane = threadIdx.x & 31;

    int base = g_i[cfg::I_ROWPTR + n];
    int deg  = g_i[cfg::I_ROWPTR + n + 1] - base;

    const float4* qr = reinterpret_cast<const float4*>(g_f + cfg::OFF_QK + (long)n * 1024) + lane * 4;
    float4 q0 = qr[0], q1 = qr[1], q2 = qr[2], q3 = qr[3];

    float prv = (lane < 3) ? pos[(long)n * 3 + lane] : 0.f;
    float prx = __shfl_sync(0xffffffffu, prv, 0);
    float pry = __shfl_sync(0xffffffffu, prv, 1);
    float prz = __shfl_sync(0xffffffffu, prv, 2);

    float m = -1e30f, d = 0.f, a0 = 0.f, a1 = 0.f, a2 = 0.f;

    for (int i = 0; i < deg; i++) {
        int c = g_i[cfg::I_COL + base + i];
        float bias = g_f[cfg::OFF_CB + base + i];
        const float4* kr = reinterpret_cast<const float4*>(g_f + cfg::OFF_QK + (long)c * 1024 + 512) + lane * 4;
        float4 k0 = kr[0], k1 = kr[1], k2 = kr[2], k3 = kr[3];
        float s = q0.x*k0.x + q0.y*k0.y + q0.z*k0.z + q0.w*k0.w
                + q1.x*k1.x + q1.y*k1.y + q1.z*k1.z + q1.w*k1.w
                + q2.x*k2.x + q2.y*k2.y + q2.z*k2.z + q2.w*k2.w
                + q3.x*k3.x + q3.y*k3.y + q3.z*k3.z + q3.w*k3.w;
        s += __shfl_xor_sync(0xffffffffu, s, 1);
        s += __shfl_xor_sync(0xffffffffu, s, 2);

        float pv = (lane < 3) ? pos[(long)c * 3 + lane] : 0.f;
        float px = __shfl_sync(0xffffffffu, pv, 0);
        float py = __shfl_sync(0xffffffffu, pv, 1);
        float pz = __shfl_sync(0xffffffffu, pv, 2);

        float lg = s * 0.125f + bias;
        float nm = fmaxf(m, lg);
        float sc = expf(m - nm);
        float p  = expf(lg - nm);
        d  = d  * sc + p;
        a0 = a0 * sc + p * px;
        a1 = a1 * sc + p * py;
        a2 = a2 * sc + p * pz;
        m = nm;
    }

    if ((lane & 3) == 0) {
        int h = lane >> 2;
        float inv = (d > 0.f) ? 1.0f / d : 0.f;
        long o = (long)n * 24 + h * 3;
        g_f[cfg::OFF_ATT + o + 0] = a0 * inv - prx;
        g_f[cfg::OFF_ATT + o + 1] = a1 * inv - pry;
        g_f[cfg::OFF_ATT + o + 2] = a2 * inv - prz;
    }
}

// ===========================================================================
// forces h1 fixup: h1f = gelu(raw + attminus @ W24) -> fp16
// ===========================================================================
constexpr int FIX_SMEM = (24 * 1025 + 16 * 24) * 4;

__global__ __launch_bounds__(256) void forces_h1_kernel(const float* __restrict__ Wfi) {
    extern __shared__ float sw[];
    float* w24 = sw;
    float* am  = sw + 24 * 1025;
    int n0 = blockIdx.x * 16;
    int t = threadIdx.x;

    for (int idx = t; idx < 24 * 1024; idx += 256) {
        int k = idx >> 10, j = idx & 1023;
        w24[k * 1025 + j] = Wfi[(long)(512 + k) * 1024 + j];
    }
    for (int idx = t; idx < 16 * 24; idx += 256) {
        int i = idx / 24, k = idx % 24;
        am[idx] = g_f[cfg::OFF_ATT + (long)(n0 + i) * 24 + k];
    }
    __syncthreads();

#pragma unroll
    for (int jj = 0; jj < 4; jj++) {
        int j = t + jj * 256;
        float w[24];
#pragma unroll
        for (int k = 0; k < 24; k++) w[k] = w24[k * 1025 + j];
        for (int i = 0; i < 16; i++) {
            long gi = (long)(n0 + i) * 1024 + j;
            float v = g_f[cfg::OFF_RAWF + gi];
#pragma unroll
            for (int k = 0; k < 24; k++) v = fmaf(am[i * 24 + k], w[k], v);
            v = gelu_tanh(v);
            g_hf[cfg::B_H1F + gi] = __float2half(v);
        }
    }
}

// ===========================================================================
// double LayerNorm -> fp16 activations
// ===========================================================================
__global__ __launch_bounds__(128) void ln_kernel(
    const float* __restrict__ x,
    const float* __restrict__ ga, const float* __restrict__ ba,
    const float* __restrict__ gm, const float* __restrict__ bm)
{
    int row = blockIdx.x;
    int t = threadIdx.x;
    const float* xr = x + (long)row * cfg::D;

    float v[4];
    float s = 0.f, ss = 0.f;
#pragma unroll
    for (int i = 0; i < 4; i++) {
        v[i] = xr[t + 128 * i];
        s += v[i];
        ss += v[i] * v[i];
    }
    __shared__ float sh[2][4];
#pragma unroll
    for (int o = 16; o > 0; o >>= 1) {
        s  += __shfl_down_sync(0xffffffffu, s, o);
        ss += __shfl_down_sync(0xffffffffu, ss, o);
    }
    if ((t & 31) == 0) { sh[0][t >> 5] = s; sh[1][t >> 5] = ss; }
    __syncthreads();
    if (t == 0) {
        float S  = sh[0][0] + sh[0][1] + sh[0][2] + sh[0][3];
        float SS = sh[1][0] + sh[1][1] + sh[1][2] + sh[1][3];
        float mean = S / cfg::D;
        float var  = SS / cfg::D - mean * mean;
        sh[0][0] = mean;
        sh[1][0] = rsqrtf(var + 1e-5f);
    }
    __syncthreads();
    float mean = sh[0][0], rstd = sh[1][0];
#pragma unroll
    for (int i = 0; i < 4; i++) {
        int c = t + 128 * i;
        float zn = (v[i] - mean) * rstd;
        g_hf[cfg::B_ZATT + (long)row * cfg::D + c] = __float2half(zn * ga[c] + ba[c]);
        g_hf[cfg::B_ZMLP + (long)row * cfg::D + c] = __float2half(zn * gm[c] + bm[c]);
    }
}

// ===========================================================================
// fused output heads
// ===========================================================================
__global__ __launch_bounds__(256) void heads_kernel(
    const float* __restrict__ Weo, const float* __restrict__ beo,
    const float* __restrict__ Wfo, const float* __restrict__ bfo,
    float* __restrict__ out)
{
    int n = blockIdx.x;
    int t = threadIdx.x;
    const float* he = g_f + cfg::OFF_H2E + (long)n * 1024;
    const float* hf = g_f + cfg::OFF_H2F + (long)n * 1024;
    float s = 0.f, s0 = 0.f, s1 = 0.f, s2 = 0.f;
    for (int j = t; j < 1024; j += 256) {
        s += he[j] * Weo[j];
        float hv = hf[j];
        s0 += hv * Wfo[j * 3 + 0];
        s1 += hv * Wfo[j * 3 + 1];
        s2 += hv * Wfo[j * 3 + 2];
    }
    __shared__ float sh[4][8];
#pragma unroll
    for (int o = 16; o > 0; o >>= 1) {
        s  += __shfl_down_sync(0xffffffffu, s,  o);
        s0 += __shfl_down_sync(0xffffffffu, s0, o);
        s1 += __shfl_down_sync(0xffffffffu, s1, o);
        s2 += __shfl_down_sync(0xffffffffu, s2, o);
    }
    if ((t & 31) == 0) {
        int w = t >> 5;
        sh[0][w] = s; sh[1][w] = s0; sh[2][w] = s1; sh[3][w] = s2;
    }
    __syncthreads();
    if (t == 0) {
        float t0 = 0.f, t1 = 0.f, t2 = 0.f, t3 = 0.f;
#pragma unroll
        for (int i = 0; i < 8; i++) { t0 += sh[0][i]; t1 += sh[1][i]; t2 += sh[2][i]; t3 += sh[3][i]; }
        out[n] = t0 + beo[0];
        out[(long)cfg::N + (long)n * 3 + 0] = t1 + bfo[0];
        out[(long)cfg::N + (long)n * 3 + 1] = t2 + bfo[1];
        out[(long)cfg::N + (long)n * 3 + 2] = t3 + bfo[2];
    }
}

// ===========================================================================
extern "C" void kernel_launch(void* const* d_in, const int* in_sizes, int n_in,
                              void* d_out, int out_size)
{
    const float* x        = (const float*)d_in[0];
    const int*   ei       = (const int*)  d_in[1];
    const float* att_bias = (const float*)d_in[2];
    const float* pos      = (const float*)d_in[3];
    const float* g_att  = (const float*)d_in[5];
    const float* b_att  = (const float*)d_in[6];
    const float* g_mlp  = (const float*)d_in[7];
    const float* b_mlp  = (const float*)d_in[8];
    const float* Wq     = (const float*)d_in[9];
    const float* bq     = (const float*)d_in[10];
    const float* Wk     = (const float*)d_in[11];
    const float* bk     = (const float*)d_in[12];
    const float* We_in  = (const float*)d_in[13];
    const float* be_in  = (const float*)d_in[14];
    const float* We_h   = (const float*)d_in[15];
    const float* be_h   = (const float*)d_in[16];
    const float* We_out = (const float*)d_in[17];
    const float* be_out = (const float*)d_in[18];
    const float* Wf_in  = (const float*)d_in[19];
    const float* bf_in  = (const float*)d_in[20];
    const float* Wf_h   = (const float*)d_in[21];
    const float* bf_h   = (const float*)d_in[22];
    const float* Wf_out = (const float*)d_in[23];
    const float* bf_out = (const float*)d_in[24];
    float* out = (float*)d_out;

    cudaFuncSetAttribute(tc_gemm<0>, cudaFuncAttributeMaxDynamicSharedMemorySize, GEMM_SMEM);
    cudaFuncSetAttribute(tc_gemm<2>, cudaFuncAttributeMaxDynamicSharedMemorySize, GEMM_SMEM);
    cudaFuncSetAttribute(tc_gemm<3>, cudaFuncAttributeMaxDynamicSharedMemorySize, GEMM_SMEM);
    cudaFuncSetAttribute(forces_h1_kernel, cudaFuncAttributeMaxDynamicSharedMemorySize, FIX_SMEM);

    const int MB = (cfg::N + 127) / 128;   // 157

    // 0: zero csr counts
    csr_zero<<<(cfg::N + 256) / 256, 256>>>();
    // 1: LayerNorm
    ln_kernel<<<cfg::N, 128>>>(x, g_att, b_att, g_mlp, b_mlp);
    // 2: biases
    bias_concat<<<20, 256>>>(bq, bk, be_in, bf_in, be_h, bf_h);
    // 3: weights
    conv_all<<<(unsigned)((3670016L + 255) / 256), 256>>>(Wq, Wk, We_in, Wf_in, We_h, Wf_h);
    // 4: csr count
    csr_count<<<(cfg::E + 255) / 256, 256>>>(ei);
    // 5: QK projection
    tc_gemm<0><<<dim3(8, MB), 256, GEMM_SMEM>>>(cfg::B_ZATT, cfg::B_WQK,
        cfg::OFF_BQK, 0, cfg::OFF_QK, 0, cfg::N, 1024, 512);
    // 6: csr scan
    csr_scan<<<1, 1024>>>();
    // 7: csr scatter
    csr_scatter<<<(cfg::E + 255) / 256, 256>>>(ei, att_bias);
    // 8: one-pass edge attention
    edge_attn_kernel<<<(cfg::N + 7) / 8, 256>>>(pos);
    // 9: fused in-projection [N,2048]
    tc_gemm<3><<<dim3(16, MB), 256, GEMM_SMEM>>>(cfg::B_ZMLP, cfg::B_WIN,
        cfg::OFF_BIN, 0, cfg::OFF_RAWF, cfg::B_H1E, cfg::N, 2048, 512);
    // 10: forces h1 fixup
    forces_h1_kernel<<<cfg::N / 16, 256, FIX_SMEM>>>(Wf_in);
    // 11: energy hidden block
    tc_gemm<2><<<dim3(8, MB), 256, GEMM_SMEM>>>(cfg::B_H1E, cfg::B_WEH,
        cfg::OFF_BEH, cfg::B_H1E, cfg::OFF_H2E, 0, cfg::N, 1024, 1024);
    // 12: forces hidden block
    tc_gemm<2><<<dim3(8, MB), 256, GEMM_SMEM>>>(cfg::B_H1F, cfg::B_WFH,
        cfg::OFF_BFH, cfg::B_H1F, cfg::OFF_H2F, 0, cfg::N, 1024, 1024);
    // 13: output heads
    heads_kernel<<<cfg::N, 256>>>(We_out, be_out, Wf_out, bf_out, out);
}

// round 9
// speedup vs baseline: 1.7494x; 1.0056x over previous
#include <cuda_runtime.h>
#include <cuda_fp16.h>
#include <math.h>
#include <stdint.h>

#define DEV_INLINE __device__ __forceinline__

namespace cfg {
constexpr int N = 20000;
constexpr int E = 600000;
constexpr int D = 512;
constexpr int H = 8;
constexpr int HID = 1024;

// ---- fp32 scratch offsets ----
constexpr long OFF_CB   = 0;                          // E (csr-permuted att_bias)
constexpr long OFF_ATT  = OFF_CB  + (long)E;          // N*24 (att/den - pos)
constexpr long OFF_RAWF = OFF_ATT + (long)N * 24;     // N*1024 (pre-gelu forces h1, partial)
constexpr long OFF_H2E  = OFF_RAWF+ (long)N * 1024;   // N*1024
constexpr long OFF_H2F  = OFF_H2E + (long)N * 1024;   // N*1024
constexpr long OFF_BQK  = OFF_H2F + (long)N * 1024;   // 1024
constexpr long OFF_BIN  = OFF_BQK + 1024;             // 2048
constexpr long OFF_BEH  = OFF_BIN + 2048;             // 1024
constexpr long OFF_BFH  = OFF_BEH + 1024;             // 1024
constexpr long FTOTAL   = OFF_BFH + 1024;

// ---- int scratch ----
constexpr long I_ROWPTR = 0;            // N+1
constexpr long I_WOFS   = N + 1;        // N+1
constexpr long I_COL    = 2 * (N + 1);  // E
constexpr long ITOTAL   = I_COL + E;

// ---- fp16 scratch offsets ----
constexpr long B_ZATT = 0;
constexpr long B_ZMLP = B_ZATT + (long)N * D;
constexpr long B_QKA  = B_ZMLP + (long)N * D;     // [N,1024] q|k fp16
constexpr long B_H1E  = B_QKA  + (long)N * 1024;
constexpr long B_H1F  = B_H1E  + (long)N * HID;
constexpr long B_WQK  = B_H1F  + (long)N * HID;   // [1024, 512]
constexpr long B_WIN  = B_WQK  + 1024L * 512;     // [2048, 512]
constexpr long B_WEH  = B_WIN  + 2048L * 512;     // [1024, 1024]
constexpr long B_WFH  = B_WEH  + 1024L * 1024;
constexpr long BTOTAL = B_WFH  + 1024L * 1024;
}

__device__ float  g_f[cfg::FTOTAL];
__device__ int    g_i[cfg::ITOTAL];
__device__ __half g_hf[cfg::BTOTAL];

// ===========================================================================
// helpers
// ===========================================================================
DEV_INLINE float gelu_tanh(float x) {
    float x3 = x * x * x;
    float t = tanhf(0.7978845608028654f * (x + 0.044715f * x3));
    return 0.5f * x * (1.0f + t);
}
DEV_INLINE uint32_t smem_u32(const void* p) {
    uint32_t a;
    asm("{ .reg .u64 t; cvta.to.shared.u64 t, %1; cvt.u32.u64 %0, t; }" : "=r"(a) : "l"(p));
    return a;
}
DEV_INLINE void cp16(uint32_t dst, const void* src, int szbytes) {
    asm volatile("cp.async.cg.shared.global [%0], [%1], 16, %2;\n" :: "r"(dst), "l"(src), "r"(szbytes));
}
DEV_INLINE void cp_commit() { asm volatile("cp.async.commit_group;\n"); }
template <int NN>
DEV_INLINE void cp_wait() { asm volatile("cp.async.wait_group %0;\n" :: "n"(NN) : "memory"); }

DEV_INLINE void ldsm_x4(uint32_t& r0, uint32_t& r1, uint32_t& r2, uint32_t& r3, uint32_t addr) {
    asm volatile("ldmatrix.sync.aligned.m8n8.x4.shared.b16 {%0,%1,%2,%3}, [%4];"
                 : "=r"(r0), "=r"(r1), "=r"(r2), "=r"(r3) : "r"(addr));
}
DEV_INLINE void mma16816(float* c, const uint32_t* a, const uint32_t* b) {
    asm volatile("mma.sync.aligned.m16n8k16.row.col.f32.f16.f16.f32 "
                 "{%0,%1,%2,%3}, {%4,%5,%6,%7}, {%8,%9}, {%0,%1,%2,%3};"
                 : "+f"(c[0]), "+f"(c[1]), "+f"(c[2]), "+f"(c[3])
                 : "r"(a[0]), "r"(a[1]), "r"(a[2]), "r"(a[3]), "r"(b[0]), "r"(b[1]));
}
// convert 8 halfs packed in a float4 to 8 floats
DEV_INLINE void h8_to_f(const float4& v, float* o) {
    const __half2* h2 = reinterpret_cast<const __half2*>(&v);
#pragma unroll
    for (int i = 0; i < 4; i++) {
        float2 f = __half22float2(h2[i]);
        o[2 * i] = f.x; o[2 * i + 1] = f.y;
    }
}

// ===========================================================================
// fp16 HMMA GEMM core (fp32 accumulate), shared by the variants below.
// tile 128x128, BK=32, 8 warps (4m x 2n), 3-stage cp.async pipeline
// ===========================================================================
constexpr int PADK = 40;
constexpr int MAT_BYTES = 128 * PADK * 2;     // 10240
constexpr int STG_BYTES = 2 * MAT_BYTES;      // 20480
constexpr int GEMM_SMEM = 3 * STG_BYTES;      // 61440

struct GemmCore {
    uint32_t sb;
    int tid, wid, lane, wm, wn, row0, col0;
    float acc[2][8][4];

    DEV_INLINE void init(const char* smem) {
        sb = smem_u32(smem);
        tid = threadIdx.x;
        wid = tid >> 5;
        lane = tid & 31;
        wm = wid & 3;
        wn = wid >> 2;
        row0 = blockIdx.y * 128;
        col0 = blockIdx.x * 128;
    }

    DEV_INLINE void run(const __half* A, const __half* B, int M, int K) {
        const int nChunks = K >> 5;
        const int aRowOff = (lane & 7) + 8 * ((lane >> 3) & 1);
        const int aKbyte  = 16 * (lane >> 4);
        const int bRowOff = (lane & 7) + 8 * (lane >> 4);
        const int bKbyte  = 16 * ((lane >> 3) & 1);

#pragma unroll
        for (int mt = 0; mt < 2; mt++)
#pragma unroll
            for (int nt = 0; nt < 8; nt++)
#pragma unroll
                for (int q = 0; q < 4; q++) acc[mt][nt][q] = 0.f;

        auto load_stage = [&](int stage, int chunk) {
            const long k0 = (long)chunk << 5;
            const uint32_t base = sb + stage * STG_BYTES;
#pragma unroll
            for (int j = 0; j < 2; j++) {
                int i = tid + j * 256;
                int r = i >> 2;
                int seg = i & 3;
                uint32_t so = r * 80 + seg * 16;
                bool va = (row0 + r) < M;
                long ar = va ? (long)(row0 + r) : 0;
                cp16(base + so,             A + ar * K + k0 + seg * 8, va ? 16 : 0);
                long br = (long)(col0 + r);
                cp16(base + MAT_BYTES + so, B + br * K + k0 + seg * 8, 16);
            }
        };

        load_stage(0, 0);
        cp_commit();
        if (nChunks > 1) { load_stage(1, 1); cp_commit(); }

        for (int c = 0; c < nChunks; c++) {
            if (c + 1 < nChunks) cp_wait<1>(); else cp_wait<0>();
            __syncthreads();

            const uint32_t st = sb + (c % 3) * STG_BYTES;
#pragma unroll
            for (int kt = 0; kt < 2; kt++) {
                const int kb = kt * 32;
                uint32_t a[2][4];
#pragma unroll
                for (int mt = 0; mt < 2; mt++) {
                    uint32_t ro = (wm * 32 + mt * 16 + aRowOff) * 80 + kb + aKbyte;
                    ldsm_x4(a[mt][0], a[mt][1], a[mt][2], a[mt][3], st + ro);
                }
                uint32_t b[8][2];
#pragma unroll
                for (int nt2 = 0; nt2 < 4; nt2++) {
                    uint32_t ro = (wn * 64 + nt2 * 16 + bRowOff) * 80 + kb + bKbyte;
                    ldsm_x4(b[2 * nt2][0], b[2 * nt2][1], b[2 * nt2 + 1][0], b[2 * nt2 + 1][1],
                            st + MAT_BYTES + ro);
                }
#pragma unroll
                for (int mt = 0; mt < 2; mt++)
#pragma unroll
                    for (int nt = 0; nt < 8; nt++)
                        mma16816(acc[mt][nt], a[mt], b[nt]);
            }
            __syncthreads();
            if (c + 2 < nChunks) {
                load_stage((c + 2) % 3, c + 2);
                cp_commit();
            }
        }
    }
};

// epilogue iteration helper (variadic: body may contain commas)
#define EPI_LOOP(...)                                                         \
    {                                                                         \
        const int cRow = core.lane >> 2;                                      \
        const int cCol = 2 * (core.lane & 3);                                 \
        _Pragma("unroll")                                                     \
        for (int mt = 0; mt < 2; mt++) {                                      \
            _Pragma("unroll")                                                 \
            for (int half = 0; half < 2; half++) {                            \
                int r = core.row0 + core.wm * 32 + mt * 16 + cRow + half * 8; \
                if (r >= M) continue;                                         \
                _Pragma("unroll")                                             \
                for (int nt = 0; nt < 8; nt++) {                              \
                    int n = core.col0 + core.wn * 64 + nt * 8 + cCol;         \
                    float v0 = core.acc[mt][nt][half * 2 + 0];                \
                    float v1 = core.acc[mt][nt][half * 2 + 1];                \
                    __VA_ARGS__                                               \
                }                                                             \
            }                                                                 \
        }                                                                     \
    }

// QK projection: C fp16 = acc + bias -> g_hf[oH + r*1024 + n]
__global__ __launch_bounds__(256) void gemm_qk(long aOff, long bOff, long biasOff, long oH, int M, int K)
{
    extern __shared__ char smem[];
    GemmCore core; core.init(smem);
    core.run(g_hf + aOff, g_hf + bOff, M, K);
    EPI_LOOP(
        v0 += g_f[biasOff + n];
        v1 += g_f[biasOff + n + 1];
        __half2 hh; hh.x = __float2half(v0); hh.y = __float2half(v1);
        *reinterpret_cast<__half2*>(g_hf + oH + (long)r * 1024 + n) = hh;
    )
}

// in-projection: n<1024 -> gelu -> fp16 h1e; n>=1024 -> raw fp32 RAWF
__global__ __launch_bounds__(256) void gemm_in(long aOff, long bOff, long biasOff,
                                               long cOff, long oH, int M, int K)
{
    extern __shared__ char smem[];
    GemmCore core; core.init(smem);
    core.run(g_hf + aOff, g_hf + bOff, M, K);
    EPI_LOOP(
        v0 += g_f[biasOff + n];
        v1 += g_f[biasOff + n + 1];
        if (n < 1024) {
            float gv0 = gelu_tanh(v0);
            float gv1 = gelu_tanh(v1);
            __half2 hh; hh.x = __float2half(gv0); hh.y = __float2half(gv1);
            *reinterpret_cast<__half2*>(g_hf + oH + (long)r * 1024 + n) = hh;
        } else {
            float2 o; o.x = v0; o.y = v1;
            *reinterpret_cast<float2*>(g_f + cOff + (long)r * 1024 + (n - 1024)) = o;
        }
    )
}

// merged hidden blocks: z=0 energy, z=1 forces. C fp32 = res(fp16,=A) + gelu(acc+bias)
__global__ __launch_bounds__(256) void gemm_hidden(
    long aE, long aF, long bE, long bF, long biasE, long biasF, long cE, long cF, int M)
{
    extern __shared__ char smem[];
    GemmCore core; core.init(smem);
    const bool z = (blockIdx.z != 0);
    const long aOff = z ? aF : aE;
    const long bOff = z ? bF : bE;
    const long biasOff = z ? biasF : biasE;
    const long cOff = z ? cF : cE;
    core.run(g_hf + aOff, g_hf + bOff, M, 1024);
    EPI_LOOP(
        v0 = gelu_tanh(v0 + g_f[biasOff + n]);
        v1 = gelu_tanh(v1 + g_f[biasOff + n + 1]);
        long gidx = (long)r * 1024 + n;
        __half2 rh = *reinterpret_cast<const __half2*>(g_hf + aOff + gidx);
        v0 += __half2float(rh.x);
        v1 += __half2float(rh.y);
        float2 o; o.x = v0; o.y = v1;
        *reinterpret_cast<float2*>(g_f + cOff + gidx) = o;
    )
}

// ===========================================================================
// weight conversion (transpose, fp16)
// ===========================================================================
__global__ void conv_all(const float* __restrict__ Wq, const float* __restrict__ Wk,
                         const float* __restrict__ Wei, const float* __restrict__ Wfi,
                         const float* __restrict__ Weh, const float* __restrict__ Wfh)
{
    long i = (long)blockIdx.x * blockDim.x + threadIdx.x;
    if (i >= 3670016L) return;
    const float* W; long o, dst; int NcS, Kd;
    if (i < 262144L)       { W = Wq;  o = i;            dst = cfg::B_WQK;          NcS = 512;  Kd = 512; }
    else if (i < 524288L)  { W = Wk;  o = i - 262144L;  dst = cfg::B_WQK + 262144; NcS = 512;  Kd = 512; }
    else if (i < 1048576L) { W = Wei; o = i - 524288L;  dst = cfg::B_WIN;          NcS = 1024; Kd = 512; }
    else if (i < 1572864L) { W = Wfi; o = i - 1048576L; dst = cfg::B_WIN + 524288; NcS = 1024; Kd = 512; }
    else if (i < 2621440L) { W = Weh; o = i - 1572864L; dst = cfg::B_WEH;          NcS = 1024; Kd = 1024; }
    else                   { W = Wfh; o = i - 2621440L; dst = cfg::B_WFH;          NcS = 1024; Kd = 1024; }
    int n = (int)(o / Kd);
    int k = (int)(o % Kd);
    g_hf[dst + o] = __float2half(W[(long)k * NcS + n]);
}

__global__ void bias_concat(const float* __restrict__ bq, const float* __restrict__ bk,
                            const float* __restrict__ bei, const float* __restrict__ bfi,
                            const float* __restrict__ beh, const float* __restrict__ bfh)
{
    int i = blockIdx.x * blockDim.x + threadIdx.x;
    if (i < 1024) g_f[cfg::OFF_BQK + i] = (i < 512) ? bq[i] : bk[i - 512];
    else if (i < 3072) { int j = i - 1024; g_f[cfg::OFF_BIN + j] = (j < 1024) ? bei[j] : bfi[j - 1024]; }
    else if (i < 4096) g_f[cfg::OFF_BEH + i - 3072] = beh[i - 3072];
    else if (i < 5120) g_f[cfg::OFF_BFH + i - 4096] = bfh[i - 4096];
}

// ===========================================================================
// CSR build
// ===========================================================================
__global__ void csr_zero() {
    int i = blockIdx.x * blockDim.x + threadIdx.x;
    if (i <= cfg::N) g_i[cfg::I_WOFS + i] = 0;
}
__global__ void csr_count(const int* __restrict__ ei) {
    int e = blockIdx.x * blockDim.x + threadIdx.x;
    if (e < cfg::E) atomicAdd(&g_i[cfg::I_WOFS + ei[e]], 1);
}
__global__ __launch_bounds__(1024) void csr_scan() {
    __shared__ int sh[1024];
    int t = threadIdx.x;
    int loc[20];
    int base = t * 20;
    int sum = 0;
#pragma unroll
    for (int j = 0; j < 20; j++) {
        int idx = base + j;
        int v = (idx < cfg::N) ? g_i[cfg::I_WOFS + idx] : 0;
        loc[j] = sum;
        sum += v;
    }
    sh[t] = sum;
    __syncthreads();
    for (int off = 1; off < 1024; off <<= 1) {
        int v = (t >= off) ? sh[t - off] : 0;
        __syncthreads();
        sh[t] += v;
        __syncthreads();
    }
    int pre = (t == 0) ? 0 : sh[t - 1];
#pragma unroll
    for (int j = 0; j < 20; j++) {
        int idx = base + j;
        if (idx < cfg::N) {
            g_i[cfg::I_ROWPTR + idx] = pre + loc[j];
            g_i[cfg::I_WOFS + idx]   = pre + loc[j];
        }
    }
    if (t == 0) g_i[cfg::I_ROWPTR + cfg::N] = cfg::E;
}
__global__ void csr_scatter(const int* __restrict__ ei, const float* __restrict__ att_bias) {
    int e = blockIdx.x * blockDim.x + threadIdx.x;
    if (e >= cfg::E) return;
    int r = ei[e];
    int p = atomicAdd(&g_i[cfg::I_WOFS + r], 1);
    g_i[cfg::I_COL + p] = ei[cfg::E + e];
    g_f[cfg::OFF_CB + p] = att_bias[e];
}

// ===========================================================================
// one-pass edge attention (fp16 q/k): warp per node, online softmax
// ===========================================================================
__global__ __launch_bounds__(256) void edge_attn_kernel(const float* __restrict__ pos) {
    int n = blockIdx.x * 8 + (threadIdx.x >> 5);
    if (n >= cfg::N) return;
    int lane = threadIdx.x & 31;

    int base = g_i[cfg::I_ROWPTR + n];
    int deg  = g_i[cfg::I_ROWPTR + n + 1] - base;

    // q: 512 fp16; lane covers 16 halfs = 2 float4 loads
    const float4* qr = reinterpret_cast<const float4*>(g_hf + cfg::B_QKA + (long)n * 1024) + lane * 2;
    float q[16];
    h8_to_f(qr[0], q);
    h8_to_f(qr[1], q + 8);

    float prv = (lane < 3) ? pos[(long)n * 3 + lane] : 0.f;
    float prx = __shfl_sync(0xffffffffu, prv, 0);
    float pry = __shfl_sync(0xffffffffu, prv, 1);
    float prz = __shfl_sync(0xffffffffu, prv, 2);

    float m = -1e30f, d = 0.f, a0 = 0.f, a1 = 0.f, a2 = 0.f;

    for (int i = 0; i < deg; i++) {
        int c = g_i[cfg::I_COL + base + i];
        float bias = g_f[cfg::OFF_CB + base + i];
        const float4* kr = reinterpret_cast<const float4*>(g_hf + cfg::B_QKA + (long)c * 1024 + 512) + lane * 2;
        float kv[16];
        h8_to_f(kr[0], kv);
        h8_to_f(kr[1], kv + 8);
        float s = 0.f;
#pragma unroll
        for (int j = 0; j < 16; j++) s = fmaf(q[j], kv[j], s);
        s += __shfl_xor_sync(0xffffffffu, s, 1);
        s += __shfl_xor_sync(0xffffffffu, s, 2);

        float pv = (lane < 3) ? pos[(long)c * 3 + lane] : 0.f;
        float px = __shfl_sync(0xffffffffu, pv, 0);
        float py = __shfl_sync(0xffffffffu, pv, 1);
        float pz = __shfl_sync(0xffffffffu, pv, 2);

        float lg = s * 0.125f + bias;
        float nm = fmaxf(m, lg);
        float sc = expf(m - nm);
        float p  = expf(lg - nm);
        d  = d  * sc + p;
        a0 = a0 * sc + p * px;
        a1 = a1 * sc + p * py;
        a2 = a2 * sc + p * pz;
        m = nm;
    }

    if ((lane & 3) == 0) {
        int h = lane >> 2;
        float inv = (d > 0.f) ? 1.0f / d : 0.f;
        long o = (long)n * 24 + h * 3;
        g_f[cfg::OFF_ATT + o + 0] = a0 * inv - prx;
        g_f[cfg::OFF_ATT + o + 1] = a1 * inv - pry;
        g_f[cfg::OFF_ATT + o + 2] = a2 * inv - prz;
    }
}

// ===========================================================================
// forces h1 fixup: h1f = gelu(raw + attminus @ W24) -> fp16
// ===========================================================================
constexpr int FIX_SMEM = (24 * 1025 + 16 * 24) * 4;

__global__ __launch_bounds__(256) void forces_h1_kernel(const float* __restrict__ Wfi) {
    extern __shared__ float sw[];
    float* w24 = sw;
    float* am  = sw + 24 * 1025;
    int n0 = blockIdx.x * 16;
    int t = threadIdx.x;

    for (int idx = t; idx < 24 * 1024; idx += 256) {
        int k = idx >> 10, j = idx & 1023;
        w24[k * 1025 + j] = Wfi[(long)(512 + k) * 1024 + j];
    }
    for (int idx = t; idx < 16 * 24; idx += 256) {
        int i = idx / 24, k = idx % 24;
        am[idx] = g_f[cfg::OFF_ATT + (long)(n0 + i) * 24 + k];
    }
    __syncthreads();

#pragma unroll
    for (int jj = 0; jj < 4; jj++) {
        int j = t + jj * 256;
        float w[24];
#pragma unroll
        for (int k = 0; k < 24; k++) w[k] = w24[k * 1025 + j];
        for (int i = 0; i < 16; i++) {
            long gi = (long)(n0 + i) * 1024 + j;
            float v = g_f[cfg::OFF_RAWF + gi];
#pragma unroll
            for (int k = 0; k < 24; k++) v = fmaf(am[i * 24 + k], w[k], v);
            v = gelu_tanh(v);
            g_hf[cfg::B_H1F + gi] = __float2half(v);
        }
    }
}

// ===========================================================================
// double LayerNorm -> fp16 activations
// ===========================================================================
__global__ __launch_bounds__(128) void ln_kernel(
    const float* __restrict__ x,
    const float* __restrict__ ga, const float* __restrict__ ba,
    const float* __restrict__ gm, const float* __restrict__ bm)
{
    int row = blockIdx.x;
    int t = threadIdx.x;
    const float* xr = x + (long)row * cfg::D;

    float v[4];
    float s = 0.f, ss = 0.f;
#pragma unroll
    for (int i = 0; i < 4; i++) {
        v[i] = xr[t + 128 * i];
        s += v[i];
        ss += v[i] * v[i];
    }
    __shared__ float sh[2][4];
#pragma unroll
    for (int o = 16; o > 0; o >>= 1) {
        s  += __shfl_down_sync(0xffffffffu, s, o);
        ss += __shfl_down_sync(0xffffffffu, ss, o);
    }
    if ((t & 31) == 0) { sh[0][t >> 5] = s; sh[1][t >> 5] = ss; }
    __syncthreads();
    if (t == 0) {
        float S  = sh[0][0] + sh[0][1] + sh[0][2] + sh[0][3];
        float SS = sh[1][0] + sh[1][1] + sh[1][2] + sh[1][3];
        float mean = S / cfg::D;
        float var  = SS / cfg::D - mean * mean;
        sh[0][0] = mean;
        sh[1][0] = rsqrtf(var + 1e-5f);
    }
    __syncthreads();
    float mean = sh[0][0], rstd = sh[1][0];
#pragma unroll
    for (int i = 0; i < 4; i++) {
        int c = t + 128 * i;
        float zn = (v[i] - mean) * rstd;
        g_hf[cfg::B_ZATT + (long)row * cfg::D + c] = __float2half(zn * ga[c] + ba[c]);
        g_hf[cfg::B_ZMLP + (long)row * cfg::D + c] = __float2half(zn * gm[c] + bm[c]);
    }
}

// ===========================================================================
// fused output heads
// ===========================================================================
__global__ __launch_bounds__(256) void heads_kernel(
    const float* __restrict__ Weo, const float* __restrict__ beo,
    const float* __restrict__ Wfo, const float* __restrict__ bfo,
    float* __restrict__ out)
{
    int n = blockIdx.x;
    int t = threadIdx.x;
    const float* he = g_f + cfg::OFF_H2E + (long)n * 1024;
    const float* hf = g_f + cfg::OFF_H2F + (long)n * 1024;
    float s = 0.f, s0 = 0.f, s1 = 0.f, s2 = 0.f;
    for (int j = t; j < 1024; j += 256) {
        s += he[j] * Weo[j];
        float hv = hf[j];
        s0 += hv * Wfo[j * 3 + 0];
        s1 += hv * Wfo[j * 3 + 1];
        s2 += hv * Wfo[j * 3 + 2];
    }
    __shared__ float sh[4][8];
#pragma unroll
    for (int o = 16; o > 0; o >>= 1) {
        s  += __shfl_down_sync(0xffffffffu, s,  o);
        s0 += __shfl_down_sync(0xffffffffu, s0, o);
        s1 += __shfl_down_sync(0xffffffffu, s1, o);
        s2 += __shfl_down_sync(0xffffffffu, s2, o);
    }
    if ((t & 31) == 0) {
        int w = t >> 5;
        sh[0][w] = s; sh[1][w] = s0; sh[2][w] = s1; sh[3][w] = s2;
    }
    __syncthreads();
    if (t == 0) {
        float t0 = 0.f, t1 = 0.f, t2 = 0.f, t3 = 0.f;
#pragma unroll
        for (int i = 0; i < 8; i++) { t0 += sh[0][i]; t1 += sh[1][i]; t2 += sh[2][i]; t3 += sh[3][i]; }
        out[n] = t0 + beo[0];
        out[(long)cfg::N + (long)n * 3 + 0] = t1 + bfo[0];
        out[(long)cfg::N + (long)n * 3 + 1] = t2 + bfo[1];
        out[(long)cfg::N + (long)n * 3 + 2] = t3 + bfo[2];
    }
}

// ===========================================================================
extern "C" void kernel_launch(void* const* d_in, const int* in_sizes, int n_in,
                              void* d_out, int out_size)
{
    const float* x        = (const float*)d_in[0];
    const int*   ei       = (const int*)  d_in[1];
    const float* att_bias = (const float*)d_in[2];
    const float* pos      = (const float*)d_in[3];
    const float* g_att  = (const float*)d_in[5];
    const float* b_att  = (const float*)d_in[6];
    const float* g_mlp  = (const float*)d_in[7];
    const float* b_mlp  = (const float*)d_in[8];
    const float* Wq     = (const float*)d_in[9];
    const float* bq     = (const float*)d_in[10];
    const float* Wk     = (const float*)d_in[11];
    const float* bk     = (const float*)d_in[12];
    const float* We_in  = (const float*)d_in[13];
    const float* be_in  = (const float*)d_in[14];
    const float* We_h   = (const float*)d_in[15];
    const float* be_h   = (const float*)d_in[16];
    const float* We_out = (const float*)d_in[17];
    const float* be_out = (const float*)d_in[18];
    const float* Wf_in  = (const float*)d_in[19];
    const float* bf_in  = (const float*)d_in[20];
    const float* Wf_h   = (const float*)d_in[21];
    const float* bf_h   = (const float*)d_in[22];
    const float* Wf_out = (const float*)d_in[23];
    const float* bf_out = (const float*)d_in[24];
    float* out = (float*)d_out;

    cudaFuncSetAttribute(gemm_qk,     cudaFuncAttributeMaxDynamicSharedMemorySize, GEMM_SMEM);
    cudaFuncSetAttribute(gemm_in,     cudaFuncAttributeMaxDynamicSharedMemorySize, GEMM_SMEM);
    cudaFuncSetAttribute(gemm_hidden, cudaFuncAttributeMaxDynamicSharedMemorySize, GEMM_SMEM);
    cudaFuncSetAttribute(forces_h1_kernel, cudaFuncAttributeMaxDynamicSharedMemorySize, FIX_SMEM);

    const int MB = (cfg::N + 127) / 128;   // 157

    // 0: zero csr counts
    csr_zero<<<(cfg::N + 256) / 256, 256>>>();
    // 1: LayerNorm
    ln_kernel<<<cfg::N, 128>>>(x, g_att, b_att, g_mlp, b_mlp);
    // 2: biases
    bias_concat<<<20, 256>>>(bq, bk, be_in, bf_in, be_h, bf_h);
    // 3: weights
    conv_all<<<(unsigned)((3670016L + 255) / 256), 256>>>(Wq, Wk, We_in, Wf_in, We_h, Wf_h);
    // 4: csr count
    csr_count<<<(cfg::E + 255) / 256, 256>>>(ei);
    // 5: QK projection -> fp16 q|k
    gemm_qk<<<dim3(8, MB), 256, GEMM_SMEM>>>(cfg::B_ZATT, cfg::B_WQK, cfg::OFF_BQK,
                                             cfg::B_QKA, cfg::N, 512);
    // 6: csr scan
    csr_scan<<<1, 1024>>>();
    // 7: csr scatter
    csr_scatter<<<(cfg::E + 255) / 256, 256>>>(ei, att_bias);
    // 8: one-pass edge attention (fp16 gathers)
    edge_attn_kernel<<<(cfg::N + 7) / 8, 256>>>(pos);
    // 9: fused in-projection [N,2048]
    gemm_in<<<dim3(16, MB), 256, GEMM_SMEM>>>(cfg::B_ZMLP, cfg::B_WIN, cfg::OFF_BIN,
                                              cfg::OFF_RAWF, cfg::B_H1E, cfg::N, 512);
    // 10: forces h1 fixup
    forces_h1_kernel<<<cfg::N / 16, 256, FIX_SMEM>>>(Wf_in);
    // 11: merged hidden blocks (z: 0=energy, 1=forces)
    gemm_hidden<<<dim3(8, MB, 2), 256, GEMM_SMEM>>>(
        cfg::B_H1E, cfg::B_H1F, cfg::B_WEH, cfg::B_WFH,
        cfg::OFF_BEH, cfg::OFF_BFH, cfg::OFF_H2E, cfg::OFF_H2F, cfg::N);
    // 12: output heads
    heads_kernel<<<cfg::N, 256>>>(We_out, be_out, Wf_out, bf_out, out);
}

// round 10
// speedup vs baseline: 1.9676x; 1.1247x over previous
#include <cuda_runtime.h>
#include <cuda_fp16.h>
#include <math.h>
#include <stdint.h>

#define DEV_INLINE __device__ __forceinline__

namespace cfg {
constexpr int N = 20000;
constexpr int E = 600000;
constexpr int D = 512;
constexpr int H = 8;
constexpr int HID = 1024;

// ---- fp32 scratch offsets ----
constexpr long OFF_CB   = 0;                          // E (csr-permuted att_bias)
constexpr long OFF_ATT  = OFF_CB  + (long)E;          // N*24 (att/den - pos)
constexpr long OFF_H2E  = OFF_ATT + (long)N * 24;     // N*1024
constexpr long OFF_H2F  = OFF_H2E + (long)N * 1024;   // N*1024
constexpr long OFF_BQK  = OFF_H2F + (long)N * 1024;   // 1024
constexpr long OFF_BIN  = OFF_BQK + 1024;             // 2048
constexpr long OFF_BEH  = OFF_BIN + 2048;             // 1024
constexpr long OFF_BFH  = OFF_BEH + 1024;             // 1024
constexpr long FTOTAL   = OFF_BFH + 1024;

// ---- int scratch ----
constexpr long I_ROWPTR = 0;            // N+1
constexpr long I_WOFS   = N + 1;        // N+1
constexpr long I_COL    = 2 * (N + 1);  // E
constexpr long ITOTAL   = I_COL + E;

// ---- fp16 scratch offsets ----
constexpr long B_ZATT = 0;
constexpr long B_ZMLP = B_ZATT + (long)N * D;
constexpr long B_QKA  = B_ZMLP + (long)N * D;     // [N,1024] q|k fp16
constexpr long B_H1E  = B_QKA  + (long)N * 1024;
constexpr long B_H1F  = B_H1E  + (long)N * HID;
constexpr long B_RAWF = B_H1F  + (long)N * HID;   // [N,1024] raw forces h1 (pre-gelu, fp16)
constexpr long B_WQK  = B_RAWF + (long)N * 1024;  // [1024, 512]
constexpr long B_WIN  = B_WQK  + 1024L * 512;     // [2048, 512]
constexpr long B_WEH  = B_WIN  + 2048L * 512;     // [1024, 1024]
constexpr long B_WFH  = B_WEH  + 1024L * 1024;
constexpr long BTOTAL = B_WFH  + 1024L * 1024;
}

__device__ float  g_f[cfg::FTOTAL];
__device__ int    g_i[cfg::ITOTAL];
__device__ __half g_hf[cfg::BTOTAL];

// ===========================================================================
// helpers
// ===========================================================================
DEV_INLINE float gelu_tanh(float x) {
    float x3 = x * x * x;
    float t = tanhf(0.7978845608028654f * (x + 0.044715f * x3));
    return 0.5f * x * (1.0f + t);
}
DEV_INLINE uint32_t smem_u32(const void* p) {
    uint32_t a;
    asm("{ .reg .u64 t; cvta.to.shared.u64 t, %1; cvt.u32.u64 %0, t; }" : "=r"(a) : "l"(p));
    return a;
}
DEV_INLINE void cp16(uint32_t dst, const void* src, int szbytes) {
    asm volatile("cp.async.cg.shared.global [%0], [%1], 16, %2;\n" :: "r"(dst), "l"(src), "r"(szbytes));
}
DEV_INLINE void cp_commit() { asm volatile("cp.async.commit_group;\n"); }
template <int NN>
DEV_INLINE void cp_wait() { asm volatile("cp.async.wait_group %0;\n" :: "n"(NN) : "memory"); }

DEV_INLINE void ldsm_x4(uint32_t& r0, uint32_t& r1, uint32_t& r2, uint32_t& r3, uint32_t addr) {
    asm volatile("ldmatrix.sync.aligned.m8n8.x4.shared.b16 {%0,%1,%2,%3}, [%4];"
                 : "=r"(r0), "=r"(r1), "=r"(r2), "=r"(r3) : "r"(addr));
}
DEV_INLINE void mma16816(float* c, const uint32_t* a, const uint32_t* b) {
    asm volatile("mma.sync.aligned.m16n8k16.row.col.f32.f16.f16.f32 "
                 "{%0,%1,%2,%3}, {%4,%5,%6,%7}, {%8,%9}, {%0,%1,%2,%3};"
                 : "+f"(c[0]), "+f"(c[1]), "+f"(c[2]), "+f"(c[3])
                 : "r"(a[0]), "r"(a[1]), "r"(a[2]), "r"(a[3]), "r"(b[0]), "r"(b[1]));
}
// convert 8 halfs packed in a float4 to 8 floats
DEV_INLINE void h8_to_f(const float4& v, float* o) {
    const __half2* h2 = reinterpret_cast<const __half2*>(&v);
#pragma unroll
    for (int i = 0; i < 4; i++) {
        float2 f = __half22float2(h2[i]);
        o[2 * i] = f.x; o[2 * i + 1] = f.y;
    }
}

// ===========================================================================
// fp16 HMMA GEMM core (fp32 accumulate).
// tile 128x128, BK=64, 8 warps (4m x 2n), 3-stage cp.async pipeline.
// Row stride 144B (64 fp16 + 8 pad) -> ldmatrix conflict-free (bank 4r+c).
// ===========================================================================
constexpr int PADROW = 144;
constexpr int MAT_BYTES = 128 * PADROW;       // 18432
constexpr int STG_BYTES = 2 * MAT_BYTES;      // 36864
constexpr int GEMM_SMEM = 3 * STG_BYTES;      // 110592

struct GemmCore {
    uint32_t sb;
    int tid, lane, wm, wn, row0, col0;
    float acc[2][8][4];

    DEV_INLINE void init(const char* smem) {
        sb = smem_u32(smem);
        tid = threadIdx.x;
        int wid = tid >> 5;
        lane = tid & 31;
        wm = wid & 3;
        wn = wid >> 2;
        row0 = blockIdx.y * 128;
        col0 = blockIdx.x * 128;
    }

    DEV_INLINE void run(const __half* A, const __half* B, int M, int K) {
        const int nChunks = K >> 6;
        const int aRowOff = (lane & 7) + 8 * ((lane >> 3) & 1);
        const int aKbyte  = 16 * (lane >> 4);
        const int bRowOff = (lane & 7) + 8 * (lane >> 4);
        const int bKbyte  = 16 * ((lane >> 3) & 1);

#pragma unroll
        for (int mt = 0; mt < 2; mt++)
#pragma unroll
            for (int nt = 0; nt < 8; nt++)
#pragma unroll
                for (int q = 0; q < 4; q++) acc[mt][nt][q] = 0.f;

        auto load_stage = [&](int stage, int chunk) {
            const long k0 = (long)chunk << 6;
            const uint32_t base = sb + stage * STG_BYTES;
#pragma unroll
            for (int j = 0; j < 4; j++) {
                int i = tid + j * 256;        // 0..1023
                int r = i >> 3;               // 0..127
                int seg = i & 7;              // 0..7
                uint32_t so = r * PADROW + seg * 16;
                bool va = (row0 + r) < M;
                long ar = va ? (long)(row0 + r) : 0;
                cp16(base + so,             A + ar * K + k0 + seg * 8, va ? 16 : 0);
                long br = (long)(col0 + r);
                cp16(base + MAT_BYTES + so, B + br * K + k0 + seg * 8, 16);
            }
        };

        load_stage(0, 0);
        cp_commit();
        if (nChunks > 1) { load_stage(1, 1); cp_commit(); }

        for (int c = 0; c < nChunks; c++) {
            if (c + 1 < nChunks) cp_wait<1>(); else cp_wait<0>();
            __syncthreads();

            const uint32_t st = sb + (c % 3) * STG_BYTES;
#pragma unroll
            for (int kt = 0; kt < 4; kt++) {
                const int kb = kt * 32;
                uint32_t a[2][4];
#pragma unroll
                for (int mt = 0; mt < 2; mt++) {
                    uint32_t ro = (wm * 32 + mt * 16 + aRowOff) * PADROW + kb + aKbyte;
                    ldsm_x4(a[mt][0], a[mt][1], a[mt][2], a[mt][3], st + ro);
                }
                uint32_t b[8][2];
#pragma unroll
                for (int nt2 = 0; nt2 < 4; nt2++) {
                    uint32_t ro = (wn * 64 + nt2 * 16 + bRowOff) * PADROW + kb + bKbyte;
                    ldsm_x4(b[2 * nt2][0], b[2 * nt2][1], b[2 * nt2 + 1][0], b[2 * nt2 + 1][1],
                            st + MAT_BYTES + ro);
                }
#pragma unroll
                for (int mt = 0; mt < 2; mt++)
#pragma unroll
                    for (int nt = 0; nt < 8; nt++)
                        mma16816(acc[mt][nt], a[mt], b[nt]);
            }
            __syncthreads();
            if (c + 2 < nChunks) {
                load_stage((c + 2) % 3, c + 2);
                cp_commit();
            }
        }
    }
};

// epilogue iteration helper (variadic: body may contain commas)
#define EPI_LOOP(...)                                                         \
    {                                                                         \
        const int cRow = core.lane >> 2;                                      \
        const int cCol = 2 * (core.lane & 3);                                 \
        _Pragma("unroll")                                                     \
        for (int mt = 0; mt < 2; mt++) {                                      \
            _Pragma("unroll")                                                 \
            for (int half = 0; half < 2; half++) {                            \
                int r = core.row0 + core.wm * 32 + mt * 16 + cRow + half * 8; \
                if (r >= M) continue;                                         \
                _Pragma("unroll")                                             \
                for (int nt = 0; nt < 8; nt++) {                              \
                    int n = core.col0 + core.wn * 64 + nt * 8 + cCol;         \
                    float v0 = core.acc[mt][nt][half * 2 + 0];                \
                    float v1 = core.acc[mt][nt][half * 2 + 1];                \
                    __VA_ARGS__                                               \
                }                                                             \
            }                                                                 \
        }                                                                     \
    }

// QK projection: C fp16 = acc + bias
__global__ __launch_bounds__(256, 2) void gemm_qk(long aOff, long bOff, long biasOff, long oH, int M, int K)
{
    extern __shared__ char smem[];
    GemmCore core; core.init(smem);
    core.run(g_hf + aOff, g_hf + bOff, M, K);
    EPI_LOOP(
        v0 += g_f[biasOff + n];
        v1 += g_f[biasOff + n + 1];
        __half2 hh; hh.x = __float2half(v0); hh.y = __float2half(v1);
        *reinterpret_cast<__half2*>(g_hf + oH + (long)r * 1024 + n) = hh;
    )
}

// in-projection: n<1024 -> gelu -> fp16 h1e; n>=1024 -> raw fp16
__global__ __launch_bounds__(256, 2) void gemm_in(long aOff, long bOff, long biasOff,
                                                  long rawOff, long oH, int M, int K)
{
    extern __shared__ char smem[];
    GemmCore core; core.init(smem);
    core.run(g_hf + aOff, g_hf + bOff, M, K);
    EPI_LOOP(
        v0 += g_f[biasOff + n];
        v1 += g_f[biasOff + n + 1];
        if (n < 1024) {
            float gv0 = gelu_tanh(v0);
            float gv1 = gelu_tanh(v1);
            __half2 hh; hh.x = __float2half(gv0); hh.y = __float2half(gv1);
            *reinterpret_cast<__half2*>(g_hf + oH + (long)r * 1024 + n) = hh;
        } else {
            __half2 hh; hh.x = __float2half(v0); hh.y = __float2half(v1);
            *reinterpret_cast<__half2*>(g_hf + rawOff + (long)r * 1024 + (n - 1024)) = hh;
        }
    )
}

// merged hidden blocks: z=0 energy, z=1 forces. C fp32 = res(fp16,=A) + gelu(acc+bias)
__global__ __launch_bounds__(256, 2) void gemm_hidden(
    long aE, long aF, long bE, long bF, long biasE, long biasF, long cE, long cF, int M)
{
    extern __shared__ char smem[];
    GemmCore core; core.init(smem);
    const bool z = (blockIdx.z != 0);
    const long aOff = z ? aF : aE;
    const long bOff = z ? bF : bE;
    const long biasOff = z ? biasF : biasE;
    const long cOff = z ? cF : cE;
    core.run(g_hf + aOff, g_hf + bOff, M, 1024);
    EPI_LOOP(
        v0 = gelu_tanh(v0 + g_f[biasOff + n]);
        v1 = gelu_tanh(v1 + g_f[biasOff + n + 1]);
        long gidx = (long)r * 1024 + n;
        __half2 rh = *reinterpret_cast<const __half2*>(g_hf + aOff + gidx);
        v0 += __half2float(rh.x);
        v1 += __half2float(rh.y);
        float2 o; o.x = v0; o.y = v1;
        *reinterpret_cast<float2*>(g_f + cOff + gidx) = o;
    )
}

// ===========================================================================
// weight conversion (transpose, fp16)
// ===========================================================================
__global__ void conv_all(const float* __restrict__ Wq, const float* __restrict__ Wk,
                         const float* __restrict__ Wei, const float* __restrict__ Wfi,
                         const float* __restrict__ Weh, const float* __restrict__ Wfh)
{
    long i = (long)blockIdx.x * blockDim.x + threadIdx.x;
    if (i >= 3670016L) return;
    const float* W; long o, dst; int NcS, Kd;
    if (i < 262144L)       { W = Wq;  o = i;            dst = cfg::B_WQK;          NcS = 512;  Kd = 512; }
    else if (i < 524288L)  { W = Wk;  o = i - 262144L;  dst = cfg::B_WQK + 262144; NcS = 512;  Kd = 512; }
    else if (i < 1048576L) { W = Wei; o = i - 524288L;  dst = cfg::B_WIN;          NcS = 1024; Kd = 512; }
    else if (i < 1572864L) { W = Wfi; o = i - 1048576L; dst = cfg::B_WIN + 524288; NcS = 1024; Kd = 512; }
    else if (i < 2621440L) { W = Weh; o = i - 1572864L; dst = cfg::B_WEH;          NcS = 1024; Kd = 1024; }
    else                   { W = Wfh; o = i - 2621440L; dst = cfg::B_WFH;          NcS = 1024; Kd = 1024; }
    int n = (int)(o / Kd);
    int k = (int)(o % Kd);
    g_hf[dst + o] = __float2half(W[(long)k * NcS + n]);
}

__global__ void bias_concat(const float* __restrict__ bq, const float* __restrict__ bk,
                            const float* __restrict__ bei, const float* __restrict__ bfi,
                            const float* __restrict__ beh, const float* __restrict__ bfh)
{
    int i = blockIdx.x * blockDim.x + threadIdx.x;
    if (i < 1024) g_f[cfg::OFF_BQK + i] = (i < 512) ? bq[i] : bk[i - 512];
    else if (i < 3072) { int j = i - 1024; g_f[cfg::OFF_BIN + j] = (j < 1024) ? bei[j] : bfi[j - 1024]; }
    else if (i < 4096) g_f[cfg::OFF_BEH + i - 3072] = beh[i - 3072];
    else if (i < 5120) g_f[cfg::OFF_BFH + i - 4096] = bfh[i - 4096];
}

// ===========================================================================
// CSR build
// ===========================================================================
__global__ void csr_zero() {
    int i = blockIdx.x * blockDim.x + threadIdx.x;
    if (i <= cfg::N) g_i[cfg::I_WOFS + i] = 0;
}
__global__ void csr_count(const int* __restrict__ ei) {
    int e = blockIdx.x * blockDim.x + threadIdx.x;
    if (e < cfg::E) atomicAdd(&g_i[cfg::I_WOFS + ei[e]], 1);
}
__global__ __launch_bounds__(1024) void csr_scan() {
    __shared__ int sh[1024];
    int t = threadIdx.x;
    int loc[20];
    int base = t * 20;
    int sum = 0;
#pragma unroll
    for (int j = 0; j < 20; j++) {
        int idx = base + j;
        int v = (idx < cfg::N) ? g_i[cfg::I_WOFS + idx] : 0;
        loc[j] = sum;
        sum += v;
    }
    sh[t] = sum;
    __syncthreads();
    for (int off = 1; off < 1024; off <<= 1) {
        int v = (t >= off) ? sh[t - off] : 0;
        __syncthreads();
        sh[t] += v;
        __syncthreads();
    }
    int pre = (t == 0) ? 0 : sh[t - 1];
#pragma unroll
    for (int j = 0; j < 20; j++) {
        int idx = base + j;
        if (idx < cfg::N) {
            g_i[cfg::I_ROWPTR + idx] = pre + loc[j];
            g_i[cfg::I_WOFS + idx]   = pre + loc[j];
        }
    }
    if (t == 0) g_i[cfg::I_ROWPTR + cfg::N] = cfg::E;
}
__global__ void csr_scatter(const int* __restrict__ ei, const float* __restrict__ att_bias) {
    int e = blockIdx.x * blockDim.x + threadIdx.x;
    if (e >= cfg::E) return;
    int r = ei[e];
    int p = atomicAdd(&g_i[cfg::I_WOFS + r], 1);
    g_i[cfg::I_COL + p] = ei[cfg::E + e];
    g_f[cfg::OFF_CB + p] = att_bias[e];
}

// ===========================================================================
// one-pass edge attention (fp16 q/k): warp per node, online softmax
// ===========================================================================
__global__ __launch_bounds__(256) void edge_attn_kernel(const float* __restrict__ pos) {
    int n = blockIdx.x * 8 + (threadIdx.x >> 5);
    if (n >= cfg::N) return;
    int lane = threadIdx.x & 31;

    int base = g_i[cfg::I_ROWPTR + n];
    int deg  = g_i[cfg::I_ROWPTR + n + 1] - base;

    const float4* qr = reinterpret_cast<const float4*>(g_hf + cfg::B_QKA + (long)n * 1024) + lane * 2;
    float q[16];
    h8_to_f(qr[0], q);
    h8_to_f(qr[1], q + 8);

    float prv = (lane < 3) ? pos[(long)n * 3 + lane] : 0.f;
    float prx = __shfl_sync(0xffffffffu, prv, 0);
    float pry = __shfl_sync(0xffffffffu, prv, 1);
    float prz = __shfl_sync(0xffffffffu, prv, 2);

    float m = -1e30f, d = 0.f, a0 = 0.f, a1 = 0.f, a2 = 0.f;

    for (int i = 0; i < deg; i++) {
        int c = g_i[cfg::I_COL + base + i];
        float bias = g_f[cfg::OFF_CB + base + i];
        const float4* kr = reinterpret_cast<const float4*>(g_hf + cfg::B_QKA + (long)c * 1024 + 512) + lane * 2;
        float kv[16];
        h8_to_f(kr[0], kv);
        h8_to_f(kr[1], kv + 8);
        float s = 0.f;
#pragma unroll
        for (int j = 0; j < 16; j++) s = fmaf(q[j], kv[j], s);
        s += __shfl_xor_sync(0xffffffffu, s, 1);
        s += __shfl_xor_sync(0xffffffffu, s, 2);

        float pv = (lane < 3) ? pos[(long)c * 3 + lane] : 0.f;
        float px = __shfl_sync(0xffffffffu, pv, 0);
        float py = __shfl_sync(0xffffffffu, pv, 1);
        float pz = __shfl_sync(0xffffffffu, pv, 2);

        float lg = s * 0.125f + bias;
        float nm = fmaxf(m, lg);
        float sc = expf(m - nm);
        float p  = expf(lg - nm);
        d  = d  * sc + p;
        a0 = a0 * sc + p * px;
        a1 = a1 * sc + p * py;
        a2 = a2 * sc + p * pz;
        m = nm;
    }

    if ((lane & 3) == 0) {
        int h = lane >> 2;
        float inv = (d > 0.f) ? 1.0f / d : 0.f;
        long o = (long)n * 24 + h * 3;
        g_f[cfg::OFF_ATT + o + 0] = a0 * inv - prx;
        g_f[cfg::OFF_ATT + o + 1] = a1 * inv - pry;
        g_f[cfg::OFF_ATT + o + 2] = a2 * inv - prz;
    }
}

// ===========================================================================
// forces h1 fixup: h1f = gelu(raw(fp16) + attminus @ W24) -> fp16
// ===========================================================================
constexpr int FIX_SMEM = (24 * 1025 + 16 * 24) * 4;

__global__ __launch_bounds__(256) void forces_h1_kernel(const float* __restrict__ Wfi) {
    extern __shared__ float sw[];
    float* w24 = sw;
    float* am  = sw + 24 * 1025;
    int n0 = blockIdx.x * 16;
    int t = threadIdx.x;

    for (int idx = t; idx < 24 * 1024; idx += 256) {
        int k = idx >> 10, j = idx & 1023;
        w24[k * 1025 + j] = Wfi[(long)(512 + k) * 1024 + j];
    }
    for (int idx = t; idx < 16 * 24; idx += 256) {
        int i = idx / 24, k = idx % 24;
        am[idx] = g_f[cfg::OFF_ATT + (long)(n0 + i) * 24 + k];
    }
    __syncthreads();

#pragma unroll
    for (int jj = 0; jj < 4; jj++) {
        int j = t + jj * 256;
        float w[24];
#pragma unroll
        for (int k = 0; k < 24; k++) w[k] = w24[k * 1025 + j];
        for (int i = 0; i < 16; i++) {
            long gi = (long)(n0 + i) * 1024 + j;
            float v = __half2float(g_hf[cfg::B_RAWF + gi]);
#pragma unroll
            for (int k = 0; k < 24; k++) v = fmaf(am[i * 24 + k], w[k], v);
            v = gelu_tanh(v);
            g_hf[cfg::B_H1F + gi] = __float2half(v);
        }
    }
}

// ===========================================================================
// double LayerNorm -> fp16 activations
// ===========================================================================
__global__ __launch_bounds__(128) void ln_kernel(
    const float* __restrict__ x,
    const float* __restrict__ ga, const float* __restrict__ ba,
    const float* __restrict__ gm, const float* __restrict__ bm)
{
    int row = blockIdx.x;
    int t = threadIdx.x;
    const float* xr = x + (long)row * cfg::D;

    float v[4];
    float s = 0.f, ss = 0.f;
#pragma unroll
    for (int i = 0; i < 4; i++) {
        v[i] = xr[t + 128 * i];
        s += v[i];
        ss += v[i] * v[i];
    }
    __shared__ float sh[2][4];
#pragma unroll
    for (int o = 16; o > 0; o >>= 1) {
        s  += __shfl_down_sync(0xffffffffu, s, o);
        ss += __shfl_down_sync(0xffffffffu, ss, o);
    }
    if ((t & 31) == 0) { sh[0][t >> 5] = s; sh[1][t >> 5] = ss; }
    __syncthreads();
    if (t == 0) {
        float S  = sh[0][0] + sh[0][1] + sh[0][2] + sh[0][3];
        float SS = sh[1][0] + sh[1][1] + sh[1][2] + sh[1][3];
        float mean = S / cfg::D;
        float var  = SS / cfg::D - mean * mean;
        sh[0][0] = mean;
        sh[1][0] = rsqrtf(var + 1e-5f);
    }
    __syncthreads();
    float mean = sh[0][0], rstd = sh[1][0];
#pragma unroll
    for (int i = 0; i < 4; i++) {
        int c = t + 128 * i;
        float zn = (v[i] - mean) * rstd;
        g_hf[cfg::B_ZATT + (long)row * cfg::D + c] = __float2half(zn * ga[c] + ba[c]);
        g_hf[cfg::B_ZMLP + (long)row * cfg::D + c] = __float2half(zn * gm[c] + bm[c]);
    }
}

// ===========================================================================
// fused output heads
// ===========================================================================
__global__ __launch_bounds__(256) void heads_kernel(
    const float* __restrict__ Weo, const float* __restrict__ beo,
    const float* __restrict__ Wfo, const float* __restrict__ bfo,
    float* __restrict__ out)
{
    int n = blockIdx.x;
    int t = threadIdx.x;
    const float* he = g_f + cfg::OFF_H2E + (long)n * 1024;
    const float* hf = g_f + cfg::OFF_H2F + (long)n * 1024;
    float s = 0.f, s0 = 0.f, s1 = 0.f, s2 = 0.f;
    for (int j = t; j < 1024; j += 256) {
        s += he[j] * Weo[j];
        float hv = hf[j];
        s0 += hv * Wfo[j * 3 + 0];
        s1 += hv * Wfo[j * 3 + 1];
        s2 += hv * Wfo[j * 3 + 2];
    }
    __shared__ float sh[4][8];
#pragma unroll
    for (int o = 16; o > 0; o >>= 1) {
        s  += __shfl_down_sync(0xffffffffu, s,  o);
        s0 += __shfl_down_sync(0xffffffffu, s0, o);
        s1 += __shfl_down_sync(0xffffffffu, s1, o);
        s2 += __shfl_down_sync(0xffffffffu, s2, o);
    }
    if ((t & 31) == 0) {
        int w = t >> 5;
        sh[0][w] = s; sh[1][w] = s0; sh[2][w] = s1; sh[3][w] = s2;
    }
    __syncthreads();
    if (t == 0) {
        float t0 = 0.f, t1 = 0.f, t2 = 0.f, t3 = 0.f;
#pragma unroll
        for (int i = 0; i < 8; i++) { t0 += sh[0][i]; t1 += sh[1][i]; t2 += sh[2][i]; t3 += sh[3][i]; }
        out[n] = t0 + beo[0];
        out[(long)cfg::N + (long)n * 3 + 0] = t1 + bfo[0];
        out[(long)cfg::N + (long)n * 3 + 1] = t2 + bfo[1];
        out[(long)cfg::N + (long)n * 3 + 2] = t3 + bfo[2];
    }
}

// ===========================================================================
extern "C" void kernel_launch(void* const* d_in, const int* in_sizes, int n_in,
                              void* d_out, int out_size)
{
    const float* x        = (const float*)d_in[0];
    const int*   ei       = (const int*)  d_in[1];
    const float* att_bias = (const float*)d_in[2];
    const float* pos      = (const float*)d_in[3];
    const float* g_att  = (const float*)d_in[5];
    const float* b_att  = (const float*)d_in[6];
    const float* g_mlp  = (const float*)d_in[7];
    const float* b_mlp  = (const float*)d_in[8];
    const float* Wq     = (const float*)d_in[9];
    const float* bq     = (const float*)d_in[10];
    const float* Wk     = (const float*)d_in[11];
    const float* bk     = (const float*)d_in[12];
    const float* We_in  = (const float*)d_in[13];
    const float* be_in  = (const float*)d_in[14];
    const float* We_h   = (const float*)d_in[15];
    const float* be_h   = (const float*)d_in[16];
    const float* We_out = (const float*)d_in[17];
    const float* be_out = (const float*)d_in[18];
    const float* Wf_in  = (const float*)d_in[19];
    const float* bf_in  = (const float*)d_in[20];
    const float* Wf_h   = (const float*)d_in[21];
    const float* bf_h   = (const float*)d_in[22];
    const float* Wf_out = (const float*)d_in[23];
    const float* bf_out = (const float*)d_in[24];
    float* out = (float*)d_out;

    cudaFuncSetAttribute(gemm_qk,     cudaFuncAttributeMaxDynamicSharedMemorySize, GEMM_SMEM);
    cudaFuncSetAttribute(gemm_in,     cudaFuncAttributeMaxDynamicSharedMemorySize, GEMM_SMEM);
    cudaFuncSetAttribute(gemm_hidden, cudaFuncAttributeMaxDynamicSharedMemorySize, GEMM_SMEM);
    cudaFuncSetAttribute(forces_h1_kernel, cudaFuncAttributeMaxDynamicSharedMemorySize, FIX_SMEM);

    const int MB = (cfg::N + 127) / 128;   // 157

    // 0: zero csr counts
    csr_zero<<<(cfg::N + 256) / 256, 256>>>();
    // 1: LayerNorm
    ln_kernel<<<cfg::N, 128>>>(x, g_att, b_att, g_mlp, b_mlp);
    // 2: biases
    bias_concat<<<20, 256>>>(bq, bk, be_in, bf_in, be_h, bf_h);
    // 3: weights
    conv_all<<<(unsigned)((3670016L + 255) / 256), 256>>>(Wq, Wk, We_in, Wf_in, We_h, Wf_h);
    // 4: csr count
    csr_count<<<(cfg::E + 255) / 256, 256>>>(ei);
    // 5: QK projection -> fp16 q|k
    gemm_qk<<<dim3(8, MB), 256, GEMM_SMEM>>>(cfg::B_ZATT, cfg::B_WQK, cfg::OFF_BQK,
                                             cfg::B_QKA, cfg::N, 512);
    // 6: csr scan
    csr_scan<<<1, 1024>>>();
    // 7: csr scatter
    csr_scatter<<<(cfg::E + 255) / 256, 256>>>(ei, att_bias);
    // 8: one-pass edge attention
    edge_attn_kernel<<<(cfg::N + 7) / 8, 256>>>(pos);
    // 9: fused in-projection [N,2048]
    gemm_in<<<dim3(16, MB), 256, GEMM_SMEM>>>(cfg::B_ZMLP, cfg::B_WIN, cfg::OFF_BIN,
                                              cfg::B_RAWF, cfg::B_H1E, cfg::N, 512);
    // 10: forces h1 fixup
    forces_h1_kernel<<<cfg::N / 16, 256, FIX_SMEM>>>(Wf_in);
    // 11: merged hidden blocks (z: 0=energy, 1=forces)
    gemm_hidden<<<dim3(8, MB, 2), 256, GEMM_SMEM>>>(
        cfg::B_H1E, cfg::B_H1F, cfg::B_WEH, cfg::B_WFH,
        cfg::OFF_BEH, cfg::OFF_BFH, cfg::OFF_H2E, cfg::OFF_H2F, cfg::N);
    // 12: output heads
    heads_kernel<<<cfg::N, 256>>>(We_out, be_out, Wf_out, bf_out, out);
}